// round 13
// baseline (speedup 1.0000x reference)
#include <cuda_runtime.h>
#include <cuda_fp16.h>
#include <math.h>
#include <stdint.h>

#define N_NODES 100000
#define N_EDGES 1600000
#define NFEAT   512
#define NHID    128
#define NCLASS  40

#define SCAN_BLK   1024
#define SCAN_NBLK  ((N_NODES + SCAN_BLK - 1) / SCAN_BLK)   // 98

// ---------------- scratch (static __device__, no allocs) ----------------
__device__ uint32_t g_H1h[(size_t)N_NODES * (NHID / 2)];   // X@W1, fp16x2
__device__ uint32_t g_Hh [(size_t)N_NODES * (NHID / 2)];   // relu(A@H1+b1), fp16x2
__device__ uint32_t g_S2h[(size_t)N_NODES * (NCLASS / 2)]; // H@W2, fp16x2 (20 words/row)
__device__ uint32_t g_W1h[(NFEAT / 2) * NHID];             // W1 fp16x2, k-pair packed
__device__ int      g_rowptr[N_NODES + 1];
__device__ int      g_fill[N_NODES];
__device__ int      g_cols[N_EDGES];
__device__ float    g_vals[N_EDGES];
__device__ int      g_bsum[SCAN_NBLK];
__device__ int      g_is64;

__device__ __forceinline__ uint32_t pack_f16x2(float lo, float hi) {
    uint32_t d;
    asm("cvt.rn.f16x2.f32 %0, %1, %2;" : "=r"(d) : "f"(hi), "f"(lo));
    return d;
}

// ---------------- init: zero counts + dtype detection ----------------
__global__ void k_init(const int* __restrict__ rowi) {
    int i = blockIdx.x * blockDim.x + threadIdx.x;
    if (i < N_NODES) g_fill[i] = 0;
    if (blockIdx.x == 0) {
        __shared__ int red[256];
        int acc = 0;
        for (int t = threadIdx.x; t < 1024; t += 256) acc |= rowi[2 * t + 1];
        red[threadIdx.x] = acc;
        __syncthreads();
        for (int s = 128; s > 0; s >>= 1) {
            if (threadIdx.x < s) red[threadIdx.x] |= red[threadIdx.x + s];
            __syncthreads();
        }
        if (threadIdx.x == 0) g_is64 = (red[0] == 0) ? 1 : 0;
    }
}

// ---------------- W1 pack: fp32 [512][128] -> fp16x2 words [256][128] ------
__global__ void k_w1pack(const float* __restrict__ W1) {
    int i = blockIdx.x * blockDim.x + threadIdx.x;
    if (i < (NFEAT / 2) * NHID) {
        int kk2 = i >> 7;
        int n   = i & 127;
        float f0 = W1[(2 * kk2) * NHID + n];
        float f1 = W1[(2 * kk2 + 1) * NHID + n];
        g_W1h[i] = pack_f16x2(f0, f1);   // lo = k even, hi = k odd
    }
}

// ---------------- CSR build (2 edges per thread) ----------------
__global__ void k_hist(const void* __restrict__ row) {
    int t = blockIdx.x * blockDim.x + threadIdx.x;
    if (t >= N_EDGES / 2) return;
    int r0, r1;
    if (g_is64) {
        int4 v = ((const int4*)row)[t];
        r0 = v.x; r1 = v.z;
    } else {
        int2 v = ((const int2*)row)[t];
        r0 = v.x; r1 = v.y;
    }
    atomicAdd(&g_fill[r0], 1);
    atomicAdd(&g_fill[r1], 1);
}

__global__ __launch_bounds__(SCAN_BLK) void k_scan1() {
    __shared__ int wsum[32];
    int tid = threadIdx.x;
    int lane = tid & 31, warp = tid >> 5;
    int i = blockIdx.x * SCAN_BLK + tid;
    int v = (i < N_NODES) ? g_fill[i] : 0;

    int incl = v;
    #pragma unroll
    for (int off = 1; off < 32; off <<= 1) {
        int t = __shfl_up_sync(0xFFFFFFFF, incl, off);
        if (lane >= off) incl += t;
    }
    if (lane == 31) wsum[warp] = incl;
    __syncthreads();
    if (warp == 0) {
        int w = wsum[lane];
        #pragma unroll
        for (int off = 1; off < 32; off <<= 1) {
            int t = __shfl_up_sync(0xFFFFFFFF, w, off);
            if (lane >= off) w += t;
        }
        wsum[lane] = w;
    }
    __syncthreads();
    int base = (warp > 0) ? wsum[warp - 1] : 0;
    int excl = base + incl - v;
    if (i < N_NODES) g_rowptr[i] = excl;
    if (tid == SCAN_BLK - 1) g_bsum[blockIdx.x] = base + incl;
}

__global__ void k_scan2() {
    __shared__ int s[128];
    int tid = threadIdx.x;
    int v = (tid < SCAN_NBLK) ? g_bsum[tid] : 0;
    s[tid] = v;
    __syncthreads();
    for (int off = 1; off < 128; off <<= 1) {
        int t = (tid >= off) ? s[tid - off] : 0;
        __syncthreads();
        s[tid] += t;
        __syncthreads();
    }
    if (tid < SCAN_NBLK) g_bsum[tid] = s[tid] - v;  // exclusive
}

__global__ void k_scan3() {
    int i = blockIdx.x * blockDim.x + threadIdx.x;
    if (i < N_NODES) {
        int v = g_rowptr[i] + g_bsum[i >> 10];
        g_rowptr[i] = v;
        g_fill[i]   = v;
    }
    if (i == 0) g_rowptr[N_NODES] = N_EDGES;
}

__global__ void k_scatter(const void* __restrict__ row,
                          const void* __restrict__ col,
                          const float* __restrict__ val) {
    int t = blockIdx.x * blockDim.x + threadIdx.x;
    if (t >= N_EDGES / 2) return;
    int r0, r1, c0, c1;
    if (g_is64) {
        int4 rv = ((const int4*)row)[t];
        int4 cv = ((const int4*)col)[t];
        r0 = rv.x; r1 = rv.z; c0 = cv.x; c1 = cv.z;
    } else {
        int2 rv = ((const int2*)row)[t];
        int2 cv = ((const int2*)col)[t];
        r0 = rv.x; r1 = rv.y; c0 = cv.x; c1 = cv.y;
    }
    float2 vv = ((const float2*)val)[t];
    int p0 = atomicAdd(&g_fill[r0], 1);
    g_cols[p0] = c0; g_vals[p0] = vv.x;
    int p1 = atomicAdd(&g_fill[r1], 1);
    g_cols[p1] = c1; g_vals[p1] = vv.y;
}

// ---------------- GEMM1 (fp16 mma.sync m16n8k16 + cp.async) ---------------
#define BM 128
#define BK 32
#define AS_STRIDE 36    // fp32 words per A row
#define BS_STRIDE 136   // fp16x2 words per B pair-row
#define NIT (NFEAT / BK)

__device__ __forceinline__ void cp_async16(void* smem_dst, const void* gsrc, int src_bytes) {
    uint32_t saddr = (uint32_t)__cvta_generic_to_shared(smem_dst);
    asm volatile("cp.async.cg.shared.global [%0], [%1], 16, %2;\n"
                 :: "r"(saddr), "l"(gsrc), "r"(src_bytes));
}
#define CP_COMMIT() asm volatile("cp.async.commit_group;\n")
#define CP_WAIT(n)  asm volatile("cp.async.wait_group %0;\n" :: "n"(n))

__device__ __forceinline__ void mma_f16(float c[4], uint32_t a0, uint32_t a1,
                                        uint32_t a2, uint32_t a3,
                                        uint32_t b0, uint32_t b1) {
    asm volatile(
        "mma.sync.aligned.m16n8k16.row.col.f32.f16.f16.f32 "
        "{%0,%1,%2,%3}, {%4,%5,%6,%7}, {%8,%9}, {%0,%1,%2,%3};\n"
        : "+f"(c[0]), "+f"(c[1]), "+f"(c[2]), "+f"(c[3])
        : "r"(a0), "r"(a1), "r"(a2), "r"(a3), "r"(b0), "r"(b1));
}

__global__ __launch_bounds__(256) void k_gemm1(const float* __restrict__ A) {
    __shared__ float    As[2][BM * AS_STRIDE];
    __shared__ uint32_t Bs[2][(BK / 2) * BS_STRIDE];

    const int tid = threadIdx.x;
    const int lane = tid & 31;
    const int wid = tid >> 5;
    const int warp_m = wid >> 1;
    const int warp_n = wid & 1;
    const int block_row = blockIdx.x * BM;
    const int lq = lane >> 2;
    const int lr = lane & 3;

    float acc[2][8][4];
    #pragma unroll
    for (int i = 0; i < 2; i++)
        #pragma unroll
        for (int j = 0; j < 8; j++)
            #pragma unroll
            for (int r = 0; r < 4; r++) acc[i][j][r] = 0.f;

    #define LOAD_STAGE(st, k0)                                                   \
    do {                                                                         \
        _Pragma("unroll")                                                        \
        for (int r = 0; r < 4; r++) {                                            \
            int f = tid + r * 256;                                               \
            int m = f >> 3, c4 = f & 7;                                          \
            int grow = block_row + m;                                            \
            int ok = grow < N_NODES;                                             \
            const float* src = A + (size_t)(ok ? grow : 0) * NFEAT + (k0) + c4 * 4; \
            cp_async16(&As[st][m * AS_STRIDE + c4 * 4], src, ok ? 16 : 0);       \
        }                                                                        \
        _Pragma("unroll")                                                        \
        for (int r = 0; r < 2; r++) {                                            \
            int f = tid + r * 256;                                               \
            int kk = f >> 5, c4 = f & 31;                                        \
            cp_async16(&Bs[st][kk * BS_STRIDE + c4 * 4],                         \
                       g_W1h + ((k0) / 2 + kk) * NHID + c4 * 4, 16);             \
        }                                                                        \
    } while (0)

    LOAD_STAGE(0, 0);
    CP_COMMIT();

    for (int it = 0; it < NIT; it++) {
        int st = it & 1;
        if (it + 1 < NIT) {
            LOAD_STAGE(st ^ 1, (it + 1) * BK);
            CP_COMMIT();
            CP_WAIT(1);
        } else {
            CP_WAIT(0);
        }
        __syncthreads();

        #pragma unroll
        for (int ks = 0; ks < 2; ks++) {
            const int kb  = ks * 16;
            const int kb2 = ks * 8;
            uint32_t b0[8], b1[8];
            #pragma unroll
            for (int j = 0; j < 8; j++) {
                int n = warp_n * 64 + j * 8 + lq;
                b0[j] = Bs[st][(kb2 + lr) * BS_STRIDE + n];
                b1[j] = Bs[st][(kb2 + lr + 4) * BS_STRIDE + n];
            }
            #pragma unroll
            for (int i = 0; i < 2; i++) {
                int m = warp_m * 32 + i * 16 + lq;
                float2 v00 = *reinterpret_cast<const float2*>(&As[st][m * AS_STRIDE + kb + 2 * lr]);
                float2 v10 = *reinterpret_cast<const float2*>(&As[st][(m + 8) * AS_STRIDE + kb + 2 * lr]);
                float2 v01 = *reinterpret_cast<const float2*>(&As[st][m * AS_STRIDE + kb + 8 + 2 * lr]);
                float2 v11 = *reinterpret_cast<const float2*>(&As[st][(m + 8) * AS_STRIDE + kb + 8 + 2 * lr]);
                uint32_t a0 = pack_f16x2(v00.x, v00.y);
                uint32_t a1 = pack_f16x2(v10.x, v10.y);
                uint32_t a2 = pack_f16x2(v01.x, v01.y);
                uint32_t a3 = pack_f16x2(v11.x, v11.y);
                #pragma unroll
                for (int j = 0; j < 8; j++)
                    mma_f16(acc[i][j], a0, a1, a2, a3, b0[j], b1[j]);
            }
        }
        __syncthreads();
    }

    // epilogue: pack column pairs (col, col+1) into fp16x2 words
    #pragma unroll
    for (int i = 0; i < 2; i++) {
        int row0 = block_row + warp_m * 32 + i * 16 + lq;
        #pragma unroll
        for (int j = 0; j < 8; j++) {
            int w = warp_n * 32 + j * 4 + lr;       // word index = col/2
            if (row0 < N_NODES)
                g_H1h[(size_t)row0 * (NHID / 2) + w] = pack_f16x2(acc[i][j][0], acc[i][j][1]);
            if (row0 + 8 < N_NODES)
                g_H1h[(size_t)(row0 + 8) * (NHID / 2) + w] = pack_f16x2(acc[i][j][2], acc[i][j][3]);
        }
    }
}

// ---------------- SpMM layer 1 (CSR gather of fp16x2 H1, MLP=4) ------------
// lane handles cols 4l..4l+3; output packed fp16x2 into g_Hh
__global__ void k_spmm1(const float* __restrict__ bias) {
    int gw = (blockIdx.x * blockDim.x + threadIdx.x) >> 5;
    int lane = threadIdx.x & 31;
    if (gw >= N_NODES) return;

    int s = g_rowptr[gw];
    int e = g_rowptr[gw + 1];
    float4 acc = make_float4(0.f, 0.f, 0.f, 0.f);

    int i = s;
    for (; i + 3 < e; i += 4) {
        int c0 = g_cols[i],     c1 = g_cols[i + 1];
        int c2 = g_cols[i + 2], c3 = g_cols[i + 3];
        float v0 = g_vals[i],     v1 = g_vals[i + 1];
        float v2 = g_vals[i + 2], v3 = g_vals[i + 3];
        uint2 w0 = reinterpret_cast<const uint2*>(g_H1h + (size_t)c0 * (NHID / 2))[lane];
        uint2 w1 = reinterpret_cast<const uint2*>(g_H1h + (size_t)c1 * (NHID / 2))[lane];
        uint2 w2 = reinterpret_cast<const uint2*>(g_H1h + (size_t)c2 * (NHID / 2))[lane];
        uint2 w3 = reinterpret_cast<const uint2*>(g_H1h + (size_t)c3 * (NHID / 2))[lane];
        float2 a0 = __half22float2(*reinterpret_cast<__half2*>(&w0.x));
        float2 b0 = __half22float2(*reinterpret_cast<__half2*>(&w0.y));
        float2 a1 = __half22float2(*reinterpret_cast<__half2*>(&w1.x));
        float2 b1 = __half22float2(*reinterpret_cast<__half2*>(&w1.y));
        float2 a2 = __half22float2(*reinterpret_cast<__half2*>(&w2.x));
        float2 b2 = __half22float2(*reinterpret_cast<__half2*>(&w2.y));
        float2 a3 = __half22float2(*reinterpret_cast<__half2*>(&w3.x));
        float2 b3 = __half22float2(*reinterpret_cast<__half2*>(&w3.y));
        acc.x = fmaf(v0, a0.x, fmaf(v1, a1.x, fmaf(v2, a2.x, fmaf(v3, a3.x, acc.x))));
        acc.y = fmaf(v0, a0.y, fmaf(v1, a1.y, fmaf(v2, a2.y, fmaf(v3, a3.y, acc.y))));
        acc.z = fmaf(v0, b0.x, fmaf(v1, b1.x, fmaf(v2, b2.x, fmaf(v3, b3.x, acc.z))));
        acc.w = fmaf(v0, b0.y, fmaf(v1, b1.y, fmaf(v2, b2.y, fmaf(v3, b3.y, acc.w))));
    }
    for (; i < e; i++) {
        float v = g_vals[i];
        uint2 w = reinterpret_cast<const uint2*>(g_H1h + (size_t)g_cols[i] * (NHID / 2))[lane];
        float2 a = __half22float2(*reinterpret_cast<__half2*>(&w.x));
        float2 b = __half22float2(*reinterpret_cast<__half2*>(&w.y));
        acc.x = fmaf(v, a.x, acc.x);
        acc.y = fmaf(v, a.y, acc.y);
        acc.z = fmaf(v, b.x, acc.z);
        acc.w = fmaf(v, b.y, acc.w);
    }
    float4 b = reinterpret_cast<const float4*>(bias)[lane];
    uint2 outw;
    outw.x = pack_f16x2(fmaxf(acc.x + b.x, 0.f), fmaxf(acc.y + b.y, 0.f));
    outw.y = pack_f16x2(fmaxf(acc.z + b.z, 0.f), fmaxf(acc.w + b.w, 0.f));
    reinterpret_cast<uint2*>(g_Hh + (size_t)gw * (NHID / 2))[lane] = outw;
}

// ---------------- GEMM2 (register-tiled): fp16 H x fp32 W2 -> fp16 S2 ------
// 320 threads: tx=tid%10 (4 classes), ty=tid/10 (rows ty+32i)
__global__ __launch_bounds__(320) void k_gemm2(const float* __restrict__ W2) {
    __shared__ float W2s[NHID * NCLASS];  // 20KB
    int tid = threadIdx.x;
    int rows0 = blockIdx.x * 128;

    for (int i = tid; i < NHID * NCLASS / 4; i += 320)
        reinterpret_cast<float4*>(W2s)[i] = reinterpret_cast<const float4*>(W2)[i];
    __syncthreads();

    int tx = tid % 10;
    int ty = tid / 10;
    const int c0 = tx * 4;

    float acc[4][4];
    #pragma unroll
    for (int i = 0; i < 4; i++)
        #pragma unroll
        for (int j = 0; j < 4; j++) acc[i][j] = 0.f;

    int r[4]; bool ok[4];
    #pragma unroll
    for (int i = 0; i < 4; i++) {
        r[i] = rows0 + ty + 32 * i;
        ok[i] = r[i] < N_NODES;
    }

    for (int k4 = 0; k4 < NHID / 4; k4++) {
        float4 h[4];
        #pragma unroll
        for (int i = 0; i < 4; i++) {
            if (ok[i]) {
                uint2 w = reinterpret_cast<const uint2*>(g_Hh + (size_t)r[i] * (NHID / 2))[k4];
                float2 lo = __half22float2(*reinterpret_cast<__half2*>(&w.x));
                float2 hi = __half22float2(*reinterpret_cast<__half2*>(&w.y));
                h[i] = make_float4(lo.x, lo.y, hi.x, hi.y);
            } else {
                h[i] = make_float4(0.f, 0.f, 0.f, 0.f);
            }
        }
        #pragma unroll
        for (int kk = 0; kk < 4; kk++) {
            int k = k4 * 4 + kk;
            float w[4];
            #pragma unroll
            for (int j = 0; j < 4; j++) w[j] = W2s[k * NCLASS + c0 + j];
            #pragma unroll
            for (int i = 0; i < 4; i++) {
                float hv = (kk == 0) ? h[i].x : (kk == 1) ? h[i].y : (kk == 2) ? h[i].z : h[i].w;
                #pragma unroll
                for (int j = 0; j < 4; j++) acc[i][j] = fmaf(hv, w[j], acc[i][j]);
            }
        }
    }
    #pragma unroll
    for (int i = 0; i < 4; i++)
        if (ok[i]) {
            uint2 outw;
            outw.x = pack_f16x2(acc[i][0], acc[i][1]);
            outw.y = pack_f16x2(acc[i][2], acc[i][3]);
            *reinterpret_cast<uint2*>(g_S2h + (size_t)r[i] * (NCLASS / 2) + 2 * tx) = outw;
        }
}

// ---------------- SpMM layer 2 + bias + log_softmax fused ------------------
// lane<10 handles classes 4l..4l+3 (one uint2 gather per edge)
__global__ void k_spmm2ls(const float* __restrict__ bias, float* __restrict__ out) {
    int gw = (blockIdx.x * blockDim.x + threadIdx.x) >> 5;
    int lane = threadIdx.x & 31;
    if (gw >= N_NODES) return;

    int s = g_rowptr[gw];
    int e = g_rowptr[gw + 1];
    const int wi = (lane < 10) ? 2 * lane : 0;   // word offset in 20-word row

    float a0 = 0.f, a1 = 0.f, a2 = 0.f, a3 = 0.f;

    int i = s;
    for (; i + 3 < e; i += 4) {
        int c0 = g_cols[i],     c1 = g_cols[i + 1];
        int c2 = g_cols[i + 2], c3 = g_cols[i + 3];
        float v0 = g_vals[i],     v1 = g_vals[i + 1];
        float v2 = g_vals[i + 2], v3 = g_vals[i + 3];
        uint2 w0 = *reinterpret_cast<const uint2*>(g_S2h + (size_t)c0 * (NCLASS / 2) + wi);
        uint2 w1 = *reinterpret_cast<const uint2*>(g_S2h + (size_t)c1 * (NCLASS / 2) + wi);
        uint2 w2 = *reinterpret_cast<const uint2*>(g_S2h + (size_t)c2 * (NCLASS / 2) + wi);
        uint2 w3 = *reinterpret_cast<const uint2*>(g_S2h + (size_t)c3 * (NCLASS / 2) + wi);
        float2 p0 = __half22float2(*reinterpret_cast<__half2*>(&w0.x));
        float2 q0 = __half22float2(*reinterpret_cast<__half2*>(&w0.y));
        float2 p1 = __half22float2(*reinterpret_cast<__half2*>(&w1.x));
        float2 q1 = __half22float2(*reinterpret_cast<__half2*>(&w1.y));
        float2 p2 = __half22float2(*reinterpret_cast<__half2*>(&w2.x));
        float2 q2 = __half22float2(*reinterpret_cast<__half2*>(&w2.y));
        float2 p3 = __half22float2(*reinterpret_cast<__half2*>(&w3.x));
        float2 q3 = __half22float2(*reinterpret_cast<__half2*>(&w3.y));
        a0 = fmaf(v0, p0.x, fmaf(v1, p1.x, fmaf(v2, p2.x, fmaf(v3, p3.x, a0))));
        a1 = fmaf(v0, p0.y, fmaf(v1, p1.y, fmaf(v2, p2.y, fmaf(v3, p3.y, a1))));
        a2 = fmaf(v0, q0.x, fmaf(v1, q1.x, fmaf(v2, q2.x, fmaf(v3, q3.x, a2))));
        a3 = fmaf(v0, q0.y, fmaf(v1, q1.y, fmaf(v2, q2.y, fmaf(v3, q3.y, a3))));
    }
    for (; i < e; i++) {
        float v = g_vals[i];
        uint2 w = *reinterpret_cast<const uint2*>(g_S2h + (size_t)g_cols[i] * (NCLASS / 2) + wi);
        float2 p = __half22float2(*reinterpret_cast<__half2*>(&w.x));
        float2 q = __half22float2(*reinterpret_cast<__half2*>(&w.y));
        a0 = fmaf(v, p.x, a0);
        a1 = fmaf(v, p.y, a1);
        a2 = fmaf(v, q.x, a2);
        a3 = fmaf(v, q.y, a3);
    }

    float v0 = -INFINITY, v1 = -INFINITY, v2 = -INFINITY, v3 = -INFINITY;
    if (lane < 10) {
        float4 b = reinterpret_cast<const float4*>(bias)[lane];
        v0 = a0 + b.x;
        v1 = a1 + b.y;
        v2 = a2 + b.z;
        v3 = a3 + b.w;
    }

    float m = fmaxf(fmaxf(v0, v1), fmaxf(v2, v3));
    #pragma unroll
    for (int off = 16; off > 0; off >>= 1)
        m = fmaxf(m, __shfl_xor_sync(0xFFFFFFFF, m, off));
    float sum = (lane < 10)
        ? (expf(v0 - m) + expf(v1 - m) + expf(v2 - m) + expf(v3 - m))
        : 0.f;
    #pragma unroll
    for (int off = 16; off > 0; off >>= 1)
        sum += __shfl_xor_sync(0xFFFFFFFF, sum, off);
    float lse = m + logf(sum);

    if (lane < 10) {
        float4 o = make_float4(v0 - lse, v1 - lse, v2 - lse, v3 - lse);
        reinterpret_cast<float4*>(out + (size_t)gw * NCLASS)[lane] = o;
    }
}

// ---------------- stream/event singletons (host resources, created once) ---
static cudaStream_t side_stream() {
    static cudaStream_t s = [] {
        cudaStream_t t;
        cudaStreamCreateWithFlags(&t, cudaStreamNonBlocking);
        return t;
    }();
    return s;
}
static cudaEvent_t fork_event() {
    static cudaEvent_t e = [] {
        cudaEvent_t t;
        cudaEventCreateWithFlags(&t, cudaEventDisableTiming);
        return t;
    }();
    return e;
}
static cudaEvent_t join_event() {
    static cudaEvent_t e = [] {
        cudaEvent_t t;
        cudaEventCreateWithFlags(&t, cudaEventDisableTiming);
        return t;
    }();
    return e;
}

// ---------------- launch ----------------
extern "C" void kernel_launch(void* const* d_in, const int* in_sizes, int n_in,
                              void* d_out, int out_size) {
    const float* x    = (const float*)d_in[0];
    const void*  arow = d_in[1];
    const void*  acol = d_in[2];
    const float* aval = (const float*)d_in[3];
    const float* W1   = (const float*)d_in[4];
    const float* b1   = (const float*)d_in[5];
    const float* W2   = (const float*)d_in[6];
    const float* b2   = (const float*)d_in[7];
    float* out = (float*)d_out;

    cudaStream_t s1 = side_stream();
    cudaEvent_t evF = fork_event();
    cudaEvent_t evJ = join_event();

    // fork: CSR build on side stream, GEMM path on main stream
    cudaEventRecord(evF, 0);
    cudaStreamWaitEvent(s1, evF, 0);

    // branch B (side): CSR build
    k_init<<<(N_NODES + 255) / 256, 256, 0, s1>>>((const int*)arow);
    k_hist<<<(N_EDGES / 2 + 255) / 256, 256, 0, s1>>>(arow);
    k_scan1<<<SCAN_NBLK, SCAN_BLK, 0, s1>>>();
    k_scan2<<<1, 128, 0, s1>>>();
    k_scan3<<<(N_NODES + 255) / 256, 256, 0, s1>>>();
    k_scatter<<<(N_EDGES / 2 + 255) / 256, 256, 0, s1>>>(arow, acol, aval);
    cudaEventRecord(evJ, s1);

    // branch A (main): W1 pack + GEMM1
    k_w1pack<<<((NFEAT / 2) * NHID + 255) / 256, 256>>>(W1);
    k_gemm1<<<(N_NODES + BM - 1) / BM, 256>>>(x);

    // join: SpMM needs both branches
    cudaStreamWaitEvent(0, evJ, 0);

    k_spmm1<<<(N_NODES * 32 + 255) / 256, 256>>>(b1);
    k_gemm2<<<(N_NODES + 127) / 128, 320>>>(W2);
    k_spmm2ls<<<(N_NODES * 32 + 255) / 256, 256>>>(b2, out);
}

// round 14
// speedup vs baseline: 1.0212x; 1.0212x over previous
#include <cuda_runtime.h>
#include <cuda_fp16.h>
#include <math.h>
#include <stdint.h>

#define N_NODES 100000
#define N_EDGES 1600000
#define NFEAT   512
#define NHID    128
#define NCLASS  40

#define SCAN_BLK   1024
#define SCAN_NBLK  ((N_NODES + SCAN_BLK - 1) / SCAN_BLK)   // 98

// ---------------- scratch (static __device__, no allocs) ----------------
__device__ uint32_t g_H1h[(size_t)N_NODES * (NHID / 2)]; // X@W1 as fp16x2
__device__ float    g_H [(size_t)N_NODES * NHID];        // relu(A@H1 + b1)
__device__ float    g_S2[(size_t)N_NODES * NCLASS];      // H @ W2
__device__ uint32_t g_W1h[(NFEAT / 2) * NHID];           // W1 fp16x2, k-pair packed
__device__ int      g_rowptr[N_NODES + 1];
__device__ int      g_fill[N_NODES];
__device__ int      g_cols[N_EDGES];
__device__ float    g_vals[N_EDGES];
__device__ int      g_bsum[SCAN_NBLK];
__device__ int      g_is64;

__device__ __forceinline__ uint32_t pack_f16x2(float lo, float hi) {
    uint32_t d;
    asm("cvt.rn.f16x2.f32 %0, %1, %2;" : "=r"(d) : "f"(hi), "f"(lo));
    return d;
}

// ---------------- init: zero counts + dtype detection ----------------
__global__ void k_init(const int* __restrict__ rowi) {
    int i = blockIdx.x * blockDim.x + threadIdx.x;
    if (i < N_NODES) g_fill[i] = 0;
    if (blockIdx.x == 0) {
        __shared__ int red[256];
        int acc = 0;
        for (int t = threadIdx.x; t < 1024; t += 256) acc |= rowi[2 * t + 1];
        red[threadIdx.x] = acc;
        __syncthreads();
        for (int s = 128; s > 0; s >>= 1) {
            if (threadIdx.x < s) red[threadIdx.x] |= red[threadIdx.x + s];
            __syncthreads();
        }
        if (threadIdx.x == 0) g_is64 = (red[0] == 0) ? 1 : 0;
    }
}

// ---------------- W1 pack: fp32 [512][128] -> fp16x2 words [256][128] ------
__global__ void k_w1pack(const float* __restrict__ W1) {
    int i = blockIdx.x * blockDim.x + threadIdx.x;
    if (i < (NFEAT / 2) * NHID) {
        int kk2 = i >> 7;
        int n   = i & 127;
        float f0 = W1[(2 * kk2) * NHID + n];
        float f1 = W1[(2 * kk2 + 1) * NHID + n];
        g_W1h[i] = pack_f16x2(f0, f1);   // lo = k even, hi = k odd
    }
}

// ---------------- CSR build (2 edges per thread) ----------------
__global__ void k_hist(const void* __restrict__ row) {
    int t = blockIdx.x * blockDim.x + threadIdx.x;
    if (t >= N_EDGES / 2) return;
    int r0, r1;
    if (g_is64) {
        int4 v = ((const int4*)row)[t];
        r0 = v.x; r1 = v.z;
    } else {
        int2 v = ((const int2*)row)[t];
        r0 = v.x; r1 = v.y;
    }
    atomicAdd(&g_fill[r0], 1);
    atomicAdd(&g_fill[r1], 1);
}

__global__ __launch_bounds__(SCAN_BLK) void k_scan1() {
    __shared__ int wsum[32];
    int tid = threadIdx.x;
    int lane = tid & 31, warp = tid >> 5;
    int i = blockIdx.x * SCAN_BLK + tid;
    int v = (i < N_NODES) ? g_fill[i] : 0;

    int incl = v;
    #pragma unroll
    for (int off = 1; off < 32; off <<= 1) {
        int t = __shfl_up_sync(0xFFFFFFFF, incl, off);
        if (lane >= off) incl += t;
    }
    if (lane == 31) wsum[warp] = incl;
    __syncthreads();
    if (warp == 0) {
        int w = wsum[lane];
        #pragma unroll
        for (int off = 1; off < 32; off <<= 1) {
            int t = __shfl_up_sync(0xFFFFFFFF, w, off);
            if (lane >= off) w += t;
        }
        wsum[lane] = w;
    }
    __syncthreads();
    int base = (warp > 0) ? wsum[warp - 1] : 0;
    int excl = base + incl - v;
    if (i < N_NODES) g_rowptr[i] = excl;
    if (tid == SCAN_BLK - 1) g_bsum[blockIdx.x] = base + incl;
}

__global__ void k_scan2() {
    __shared__ int s[128];
    int tid = threadIdx.x;
    int v = (tid < SCAN_NBLK) ? g_bsum[tid] : 0;
    s[tid] = v;
    __syncthreads();
    for (int off = 1; off < 128; off <<= 1) {
        int t = (tid >= off) ? s[tid - off] : 0;
        __syncthreads();
        s[tid] += t;
        __syncthreads();
    }
    if (tid < SCAN_NBLK) g_bsum[tid] = s[tid] - v;  // exclusive
}

__global__ void k_scan3() {
    int i = blockIdx.x * blockDim.x + threadIdx.x;
    if (i < N_NODES) {
        int v = g_rowptr[i] + g_bsum[i >> 10];
        g_rowptr[i] = v;
        g_fill[i]   = v;
    }
    if (i == 0) g_rowptr[N_NODES] = N_EDGES;
}

__global__ void k_scatter(const void* __restrict__ row,
                          const void* __restrict__ col,
                          const float* __restrict__ val) {
    int t = blockIdx.x * blockDim.x + threadIdx.x;
    if (t >= N_EDGES / 2) return;
    int r0, r1, c0, c1;
    if (g_is64) {
        int4 rv = ((const int4*)row)[t];
        int4 cv = ((const int4*)col)[t];
        r0 = rv.x; r1 = rv.z; c0 = cv.x; c1 = cv.z;
    } else {
        int2 rv = ((const int2*)row)[t];
        int2 cv = ((const int2*)col)[t];
        r0 = rv.x; r1 = rv.y; c0 = cv.x; c1 = cv.y;
    }
    float2 vv = ((const float2*)val)[t];
    int p0 = atomicAdd(&g_fill[r0], 1);
    g_cols[p0] = c0; g_vals[p0] = vv.x;
    int p1 = atomicAdd(&g_fill[r1], 1);
    g_cols[p1] = c1; g_vals[p1] = vv.y;
}

// ---------------- GEMM1 (fp16 mma.sync m16n8k16 + cp.async) ---------------
#define BM 128
#define BK 32
#define AS_STRIDE 36    // fp32 words per A row
#define BS_STRIDE 136   // fp16x2 words per B pair-row
#define NIT (NFEAT / BK)

__device__ __forceinline__ void cp_async16(void* smem_dst, const void* gsrc, int src_bytes) {
    uint32_t saddr = (uint32_t)__cvta_generic_to_shared(smem_dst);
    asm volatile("cp.async.cg.shared.global [%0], [%1], 16, %2;\n"
                 :: "r"(saddr), "l"(gsrc), "r"(src_bytes));
}
#define CP_COMMIT() asm volatile("cp.async.commit_group;\n")
#define CP_WAIT(n)  asm volatile("cp.async.wait_group %0;\n" :: "n"(n))

__device__ __forceinline__ void mma_f16(float c[4], uint32_t a0, uint32_t a1,
                                        uint32_t a2, uint32_t a3,
                                        uint32_t b0, uint32_t b1) {
    asm volatile(
        "mma.sync.aligned.m16n8k16.row.col.f32.f16.f16.f32 "
        "{%0,%1,%2,%3}, {%4,%5,%6,%7}, {%8,%9}, {%0,%1,%2,%3};\n"
        : "+f"(c[0]), "+f"(c[1]), "+f"(c[2]), "+f"(c[3])
        : "r"(a0), "r"(a1), "r"(a2), "r"(a3), "r"(b0), "r"(b1));
}

__global__ __launch_bounds__(256) void k_gemm1(const float* __restrict__ A) {
    __shared__ float    As[2][BM * AS_STRIDE];
    __shared__ uint32_t Bs[2][(BK / 2) * BS_STRIDE];

    const int tid = threadIdx.x;
    const int lane = tid & 31;
    const int wid = tid >> 5;
    const int warp_m = wid >> 1;
    const int warp_n = wid & 1;
    const int block_row = blockIdx.x * BM;
    const int lq = lane >> 2;
    const int lr = lane & 3;

    float acc[2][8][4];
    #pragma unroll
    for (int i = 0; i < 2; i++)
        #pragma unroll
        for (int j = 0; j < 8; j++)
            #pragma unroll
            for (int r = 0; r < 4; r++) acc[i][j][r] = 0.f;

    #define LOAD_STAGE(st, k0)                                                   \
    do {                                                                         \
        _Pragma("unroll")                                                        \
        for (int r = 0; r < 4; r++) {                                            \
            int f = tid + r * 256;                                               \
            int m = f >> 3, c4 = f & 7;                                          \
            int grow = block_row + m;                                            \
            int ok = grow < N_NODES;                                             \
            const float* src = A + (size_t)(ok ? grow : 0) * NFEAT + (k0) + c4 * 4; \
            cp_async16(&As[st][m * AS_STRIDE + c4 * 4], src, ok ? 16 : 0);       \
        }                                                                        \
        _Pragma("unroll")                                                        \
        for (int r = 0; r < 2; r++) {                                            \
            int f = tid + r * 256;                                               \
            int kk = f >> 5, c4 = f & 31;                                        \
            cp_async16(&Bs[st][kk * BS_STRIDE + c4 * 4],                         \
                       g_W1h + ((k0) / 2 + kk) * NHID + c4 * 4, 16);             \
        }                                                                        \
    } while (0)

    LOAD_STAGE(0, 0);
    CP_COMMIT();

    for (int it = 0; it < NIT; it++) {
        int st = it & 1;
        if (it + 1 < NIT) {
            LOAD_STAGE(st ^ 1, (it + 1) * BK);
            CP_COMMIT();
            CP_WAIT(1);
        } else {
            CP_WAIT(0);
        }
        __syncthreads();

        #pragma unroll
        for (int ks = 0; ks < 2; ks++) {
            const int kb  = ks * 16;
            const int kb2 = ks * 8;
            uint32_t b0[8], b1[8];
            #pragma unroll
            for (int j = 0; j < 8; j++) {
                int n = warp_n * 64 + j * 8 + lq;
                b0[j] = Bs[st][(kb2 + lr) * BS_STRIDE + n];
                b1[j] = Bs[st][(kb2 + lr + 4) * BS_STRIDE + n];
            }
            #pragma unroll
            for (int i = 0; i < 2; i++) {
                int m = warp_m * 32 + i * 16 + lq;
                float2 v00 = *reinterpret_cast<const float2*>(&As[st][m * AS_STRIDE + kb + 2 * lr]);
                float2 v10 = *reinterpret_cast<const float2*>(&As[st][(m + 8) * AS_STRIDE + kb + 2 * lr]);
                float2 v01 = *reinterpret_cast<const float2*>(&As[st][m * AS_STRIDE + kb + 8 + 2 * lr]);
                float2 v11 = *reinterpret_cast<const float2*>(&As[st][(m + 8) * AS_STRIDE + kb + 8 + 2 * lr]);
                uint32_t a0 = pack_f16x2(v00.x, v00.y);
                uint32_t a1 = pack_f16x2(v10.x, v10.y);
                uint32_t a2 = pack_f16x2(v01.x, v01.y);
                uint32_t a3 = pack_f16x2(v11.x, v11.y);
                #pragma unroll
                for (int j = 0; j < 8; j++)
                    mma_f16(acc[i][j], a0, a1, a2, a3, b0[j], b1[j]);
            }
        }
        __syncthreads();
    }

    // epilogue: pack column pairs (col, col+1) into fp16x2 words
    #pragma unroll
    for (int i = 0; i < 2; i++) {
        int row0 = block_row + warp_m * 32 + i * 16 + lq;
        #pragma unroll
        for (int j = 0; j < 8; j++) {
            int w = warp_n * 32 + j * 4 + lr;       // word index = col/2
            if (row0 < N_NODES)
                g_H1h[(size_t)row0 * (NHID / 2) + w] = pack_f16x2(acc[i][j][0], acc[i][j][1]);
            if (row0 + 8 < N_NODES)
                g_H1h[(size_t)(row0 + 8) * (NHID / 2) + w] = pack_f16x2(acc[i][j][2], acc[i][j][3]);
        }
    }
}

// ---------------- SpMM layer 1 (fp16x2 H1 gather; int4-batched edge loads) -
__global__ void k_spmm1(const float* __restrict__ bias) {
    int gw = (blockIdx.x * blockDim.x + threadIdx.x) >> 5;
    int lane = threadIdx.x & 31;
    if (gw >= N_NODES) return;

    int s = g_rowptr[gw];
    int e = g_rowptr[gw + 1];
    float4 acc = make_float4(0.f, 0.f, 0.f, 0.f);

    #define GATHER1(c, v)                                                        \
    do {                                                                         \
        uint2 w = reinterpret_cast<const uint2*>(g_H1h + (size_t)(c) * (NHID / 2))[lane]; \
        float2 a = __half22float2(*reinterpret_cast<__half2*>(&w.x));            \
        float2 b_ = __half22float2(*reinterpret_cast<__half2*>(&w.y));           \
        acc.x = fmaf((v), a.x, acc.x);                                           \
        acc.y = fmaf((v), a.y, acc.y);                                           \
        acc.z = fmaf((v), b_.x, acc.z);                                          \
        acc.w = fmaf((v), b_.y, acc.w);                                          \
    } while (0)

    int i = s;
    // align to 4-edge boundary (g_cols/g_vals are 16B-aligned at i%4==0)
    for (; i < e && (i & 3); i++) GATHER1(g_cols[i], g_vals[i]);
    for (; i + 3 < e; i += 4) {
        int4   cc = *reinterpret_cast<const int4*>(g_cols + i);    // broadcast
        float4 vv = *reinterpret_cast<const float4*>(g_vals + i);  // broadcast
        uint2 w0 = reinterpret_cast<const uint2*>(g_H1h + (size_t)cc.x * (NHID / 2))[lane];
        uint2 w1 = reinterpret_cast<const uint2*>(g_H1h + (size_t)cc.y * (NHID / 2))[lane];
        uint2 w2 = reinterpret_cast<const uint2*>(g_H1h + (size_t)cc.z * (NHID / 2))[lane];
        uint2 w3 = reinterpret_cast<const uint2*>(g_H1h + (size_t)cc.w * (NHID / 2))[lane];
        float2 a0 = __half22float2(*reinterpret_cast<__half2*>(&w0.x));
        float2 b0 = __half22float2(*reinterpret_cast<__half2*>(&w0.y));
        float2 a1 = __half22float2(*reinterpret_cast<__half2*>(&w1.x));
        float2 b1 = __half22float2(*reinterpret_cast<__half2*>(&w1.y));
        float2 a2 = __half22float2(*reinterpret_cast<__half2*>(&w2.x));
        float2 b2 = __half22float2(*reinterpret_cast<__half2*>(&w2.y));
        float2 a3 = __half22float2(*reinterpret_cast<__half2*>(&w3.x));
        float2 b3 = __half22float2(*reinterpret_cast<__half2*>(&w3.y));
        acc.x = fmaf(vv.x, a0.x, fmaf(vv.y, a1.x, fmaf(vv.z, a2.x, fmaf(vv.w, a3.x, acc.x))));
        acc.y = fmaf(vv.x, a0.y, fmaf(vv.y, a1.y, fmaf(vv.z, a2.y, fmaf(vv.w, a3.y, acc.y))));
        acc.z = fmaf(vv.x, b0.x, fmaf(vv.y, b1.x, fmaf(vv.z, b2.x, fmaf(vv.w, b3.x, acc.z))));
        acc.w = fmaf(vv.x, b0.y, fmaf(vv.y, b1.y, fmaf(vv.z, b2.y, fmaf(vv.w, b3.y, acc.w))));
    }
    for (; i < e; i++) GATHER1(g_cols[i], g_vals[i]);
    #undef GATHER1

    float4 b = reinterpret_cast<const float4*>(bias)[lane];
    float4 r;
    r.x = fmaxf(acc.x + b.x, 0.f);
    r.y = fmaxf(acc.y + b.y, 0.f);
    r.z = fmaxf(acc.z + b.z, 0.f);
    r.w = fmaxf(acc.w + b.w, 0.f);
    reinterpret_cast<float4*>(g_H + (size_t)gw * NHID)[lane] = r;
}

// ---------------- GEMM2 (register-tiled): [100000,128]x[128,40] -> g_S2 ---
__global__ __launch_bounds__(256) void k_gemm2(const float* __restrict__ W2) {
    __shared__ float W2s[NHID * NCLASS];  // 20KB
    int tid = threadIdx.x;
    int rows0 = blockIdx.x * 128;

    for (int i = tid; i < NHID * NCLASS / 4; i += 256)
        reinterpret_cast<float4*>(W2s)[i] = reinterpret_cast<const float4*>(W2)[i];
    __syncthreads();

    int tx = tid & 7;
    int ty = tid >> 3;
    const int c0 = tx * 5;

    float acc[4][5];
    #pragma unroll
    for (int i = 0; i < 4; i++)
        #pragma unroll
        for (int j = 0; j < 5; j++) acc[i][j] = 0.f;

    int r[4]; bool ok[4];
    #pragma unroll
    for (int i = 0; i < 4; i++) {
        r[i] = rows0 + ty + 32 * i;
        ok[i] = r[i] < N_NODES;
    }

    for (int k4 = 0; k4 < NHID / 4; k4++) {
        float4 h[4];
        #pragma unroll
        for (int i = 0; i < 4; i++)
            h[i] = ok[i] ? reinterpret_cast<const float4*>(g_H + (size_t)r[i] * NHID)[k4]
                         : make_float4(0.f, 0.f, 0.f, 0.f);
        #pragma unroll
        for (int kk = 0; kk < 4; kk++) {
            int k = k4 * 4 + kk;
            float w[5];
            #pragma unroll
            for (int j = 0; j < 5; j++) w[j] = W2s[k * NCLASS + c0 + j];
            #pragma unroll
            for (int i = 0; i < 4; i++) {
                float hv = (kk == 0) ? h[i].x : (kk == 1) ? h[i].y : (kk == 2) ? h[i].z : h[i].w;
                #pragma unroll
                for (int j = 0; j < 5; j++) acc[i][j] = fmaf(hv, w[j], acc[i][j]);
            }
        }
    }
    #pragma unroll
    for (int i = 0; i < 4; i++)
        if (ok[i]) {
            #pragma unroll
            for (int j = 0; j < 5; j++)
                g_S2[(size_t)r[i] * NCLASS + c0 + j] = acc[i][j];
        }
}

// ---------------- SpMM layer 2 + log_softmax (int4-batched edge loads) -----
__global__ void k_spmm2ls(const float* __restrict__ bias, float* __restrict__ out) {
    int gw = (blockIdx.x * blockDim.x + threadIdx.x) >> 5;
    int lane = threadIdx.x & 31;
    if (gw >= N_NODES) return;

    int s = g_rowptr[gw];
    int e = g_rowptr[gw + 1];
    float a0 = 0.f, a1 = 0.f;

    #define GATHER2(c, v)                                                        \
    do {                                                                         \
        const float* d = g_S2 + (size_t)(c) * NCLASS;                            \
        a0 = fmaf((v), d[lane], a0);                                             \
        if (lane < 8) a1 = fmaf((v), d[lane + 32], a1);                          \
    } while (0)

    int i = s;
    for (; i < e && (i & 3); i++) GATHER2(g_cols[i], g_vals[i]);
    for (; i + 3 < e; i += 4) {
        int4   cc = *reinterpret_cast<const int4*>(g_cols + i);
        float4 vv = *reinterpret_cast<const float4*>(g_vals + i);
        const float* d0 = g_S2 + (size_t)cc.x * NCLASS;
        const float* d1 = g_S2 + (size_t)cc.y * NCLASS;
        const float* d2 = g_S2 + (size_t)cc.z * NCLASS;
        const float* d3 = g_S2 + (size_t)cc.w * NCLASS;
        float p0 = d0[lane], p1 = d1[lane], p2 = d2[lane], p3 = d3[lane];
        float q0 = 0.f, q1 = 0.f, q2 = 0.f, q3 = 0.f;
        if (lane < 8) {
            q0 = d0[lane + 32]; q1 = d1[lane + 32];
            q2 = d2[lane + 32]; q3 = d3[lane + 32];
        }
        a0 = fmaf(vv.x, p0, fmaf(vv.y, p1, fmaf(vv.z, p2, fmaf(vv.w, p3, a0))));
        a1 = fmaf(vv.x, q0, fmaf(vv.y, q1, fmaf(vv.z, q2, fmaf(vv.w, q3, a1))));
    }
    for (; i < e; i++) GATHER2(g_cols[i], g_vals[i]);
    #undef GATHER2

    float v0 = a0 + bias[lane];
    float v1 = (lane < 8) ? (a1 + bias[lane + 32]) : -INFINITY;

    float m = fmaxf(v0, v1);
    #pragma unroll
    for (int off = 16; off > 0; off >>= 1)
        m = fmaxf(m, __shfl_xor_sync(0xFFFFFFFF, m, off));
    float sum = expf(v0 - m) + ((lane < 8) ? expf(v1 - m) : 0.f);
    #pragma unroll
    for (int off = 16; off > 0; off >>= 1)
        sum += __shfl_xor_sync(0xFFFFFFFF, sum, off);
    float lse = m + logf(sum);

    float* p = out + (size_t)gw * NCLASS;
    p[lane] = v0 - lse;
    if (lane < 8) p[lane + 32] = v1 - lse;
}

// ---------------- stream/event singletons (host resources, created once) ---
static cudaStream_t side_stream() {
    static cudaStream_t s = [] {
        cudaStream_t t;
        cudaStreamCreateWithFlags(&t, cudaStreamNonBlocking);
        return t;
    }();
    return s;
}
static cudaEvent_t fork_event() {
    static cudaEvent_t e = [] {
        cudaEvent_t t;
        cudaEventCreateWithFlags(&t, cudaEventDisableTiming);
        return t;
    }();
    return e;
}
static cudaEvent_t join_event() {
    static cudaEvent_t e = [] {
        cudaEvent_t t;
        cudaEventCreateWithFlags(&t, cudaEventDisableTiming);
        return t;
    }();
    return e;
}

// ---------------- launch ----------------
extern "C" void kernel_launch(void* const* d_in, const int* in_sizes, int n_in,
                              void* d_out, int out_size) {
    const float* x    = (const float*)d_in[0];
    const void*  arow = d_in[1];
    const void*  acol = d_in[2];
    const float* aval = (const float*)d_in[3];
    const float* W1   = (const float*)d_in[4];
    const float* b1   = (const float*)d_in[5];
    const float* W2   = (const float*)d_in[6];
    const float* b2   = (const float*)d_in[7];
    float* out = (float*)d_out;

    cudaStream_t s1 = side_stream();
    cudaEvent_t evF = fork_event();
    cudaEvent_t evJ = join_event();

    // fork: CSR build on side stream, GEMM path on main stream
    cudaEventRecord(evF, 0);
    cudaStreamWaitEvent(s1, evF, 0);

    // branch B (side): CSR build
    k_init<<<(N_NODES + 255) / 256, 256, 0, s1>>>((const int*)arow);
    k_hist<<<(N_EDGES / 2 + 255) / 256, 256, 0, s1>>>(arow);
    k_scan1<<<SCAN_NBLK, SCAN_BLK, 0, s1>>>();
    k_scan2<<<1, 128, 0, s1>>>();
    k_scan3<<<(N_NODES + 255) / 256, 256, 0, s1>>>();
    k_scatter<<<(N_EDGES / 2 + 255) / 256, 256, 0, s1>>>(arow, acol, aval);
    cudaEventRecord(evJ, s1);

    // branch A (main): W1 pack + GEMM1
    k_w1pack<<<((NFEAT / 2) * NHID + 255) / 256, 256>>>(W1);
    k_gemm1<<<(N_NODES + BM - 1) / BM, 256>>>(x);

    // join: SpMM needs both branches
    cudaStreamWaitEvent(0, evJ, 0);

    k_spmm1<<<(N_NODES * 32 + 255) / 256, 256>>>(b1);
    k_gemm2<<<(N_NODES + 127) / 128, 256>>>(W2);
    k_spmm2ls<<<(N_NODES * 32 + 255) / 256, 256>>>(b2, out);
}

// round 15
// speedup vs baseline: 1.0637x; 1.0416x over previous
#include <cuda_runtime.h>
#include <cuda_fp16.h>
#include <math.h>
#include <stdint.h>

#define N_NODES 100000
#define N_EDGES 1600000
#define NFEAT   512
#define NHID    128
#define NCLASS  40

#define SCAN_BLK   1024
#define SCAN_NBLK  ((N_NODES + SCAN_BLK - 1) / SCAN_BLK)   // 98

// ---------------- scratch (static __device__, no allocs) ----------------
__device__ uint32_t g_H1h[(size_t)N_NODES * (NHID / 2)]; // X@W1 as fp16x2
__device__ float    g_H [(size_t)N_NODES * NHID];        // relu(A@H1 + b1)
__device__ float    g_S2[(size_t)N_NODES * NCLASS];      // H @ W2
__device__ uint32_t g_W1h[(NFEAT / 2) * NHID];           // W1 fp16x2, k-pair packed
__device__ int      g_rowptr[N_NODES + 1];
__device__ int      g_fill[N_NODES];
__device__ int      g_cols[N_EDGES];
__device__ float    g_vals[N_EDGES];
__device__ int      g_bsum[SCAN_NBLK];
__device__ int      g_is64;

__device__ __forceinline__ uint32_t pack_f16x2(float lo, float hi) {
    uint32_t d;
    asm("cvt.rn.f16x2.f32 %0, %1, %2;" : "=r"(d) : "f"(hi), "f"(lo));
    return d;
}

// ---------------- init: zero counts + dtype detection ----------------
__global__ void k_init(const int* __restrict__ rowi) {
    int i = blockIdx.x * blockDim.x + threadIdx.x;
    if (i < N_NODES) g_fill[i] = 0;
    if (blockIdx.x == 0) {
        __shared__ int red[256];
        int acc = 0;
        for (int t = threadIdx.x; t < 1024; t += 256) acc |= rowi[2 * t + 1];
        red[threadIdx.x] = acc;
        __syncthreads();
        for (int s = 128; s > 0; s >>= 1) {
            if (threadIdx.x < s) red[threadIdx.x] |= red[threadIdx.x + s];
            __syncthreads();
        }
        if (threadIdx.x == 0) g_is64 = (red[0] == 0) ? 1 : 0;
    }
}

// ---------------- W1 pack: fp32 [512][128] -> fp16x2 words [256][128] ------
__global__ void k_w1pack(const float* __restrict__ W1) {
    int i = blockIdx.x * blockDim.x + threadIdx.x;
    if (i < (NFEAT / 2) * NHID) {
        int kk2 = i >> 7;
        int n   = i & 127;
        float f0 = W1[(2 * kk2) * NHID + n];
        float f1 = W1[(2 * kk2 + 1) * NHID + n];
        g_W1h[i] = pack_f16x2(f0, f1);   // lo = k even, hi = k odd
    }
}

// ---------------- CSR build (2 edges per thread) ----------------
__global__ void k_hist(const void* __restrict__ row) {
    int t = blockIdx.x * blockDim.x + threadIdx.x;
    if (t >= N_EDGES / 2) return;
    int r0, r1;
    if (g_is64) {
        int4 v = ((const int4*)row)[t];
        r0 = v.x; r1 = v.z;
    } else {
        int2 v = ((const int2*)row)[t];
        r0 = v.x; r1 = v.y;
    }
    atomicAdd(&g_fill[r0], 1);
    atomicAdd(&g_fill[r1], 1);
}

__global__ __launch_bounds__(SCAN_BLK) void k_scan1() {
    __shared__ int wsum[32];
    int tid = threadIdx.x;
    int lane = tid & 31, warp = tid >> 5;
    int i = blockIdx.x * SCAN_BLK + tid;
    int v = (i < N_NODES) ? g_fill[i] : 0;

    int incl = v;
    #pragma unroll
    for (int off = 1; off < 32; off <<= 1) {
        int t = __shfl_up_sync(0xFFFFFFFF, incl, off);
        if (lane >= off) incl += t;
    }
    if (lane == 31) wsum[warp] = incl;
    __syncthreads();
    if (warp == 0) {
        int w = wsum[lane];
        #pragma unroll
        for (int off = 1; off < 32; off <<= 1) {
            int t = __shfl_up_sync(0xFFFFFFFF, w, off);
            if (lane >= off) w += t;
        }
        wsum[lane] = w;
    }
    __syncthreads();
    int base = (warp > 0) ? wsum[warp - 1] : 0;
    int excl = base + incl - v;
    if (i < N_NODES) g_rowptr[i] = excl;
    if (tid == SCAN_BLK - 1) g_bsum[blockIdx.x] = base + incl;
}

__global__ void k_scan2() {
    __shared__ int s[128];
    int tid = threadIdx.x;
    int v = (tid < SCAN_NBLK) ? g_bsum[tid] : 0;
    s[tid] = v;
    __syncthreads();
    for (int off = 1; off < 128; off <<= 1) {
        int t = (tid >= off) ? s[tid - off] : 0;
        __syncthreads();
        s[tid] += t;
        __syncthreads();
    }
    if (tid < SCAN_NBLK) g_bsum[tid] = s[tid] - v;  // exclusive
}

__global__ void k_scan3() {
    int i = blockIdx.x * blockDim.x + threadIdx.x;
    if (i < N_NODES) {
        int v = g_rowptr[i] + g_bsum[i >> 10];
        g_rowptr[i] = v;
        g_fill[i]   = v;
    }
    if (i == 0) g_rowptr[N_NODES] = N_EDGES;
}

__global__ void k_scatter(const void* __restrict__ row,
                          const void* __restrict__ col,
                          const float* __restrict__ val) {
    int t = blockIdx.x * blockDim.x + threadIdx.x;
    if (t >= N_EDGES / 2) return;
    int r0, r1, c0, c1;
    if (g_is64) {
        int4 rv = ((const int4*)row)[t];
        int4 cv = ((const int4*)col)[t];
        r0 = rv.x; r1 = rv.z; c0 = cv.x; c1 = cv.z;
    } else {
        int2 rv = ((const int2*)row)[t];
        int2 cv = ((const int2*)col)[t];
        r0 = rv.x; r1 = rv.y; c0 = cv.x; c1 = cv.y;
    }
    float2 vv = ((const float2*)val)[t];
    int p0 = atomicAdd(&g_fill[r0], 1);
    g_cols[p0] = c0; g_vals[p0] = vv.x;
    int p1 = atomicAdd(&g_fill[r1], 1);
    g_cols[p1] = c1; g_vals[p1] = vv.y;
}

// ---------------- GEMM1 (fp16 mma.sync; fp16 A in smem; single wave) -------
#define BM 128
#define BK 32
#define ASW_STRIDE 20   // fp16x2 words per A row (16 + 4 pad; banks 20q+r distinct)
#define BS_STRIDE 136   // fp16x2 words per B pair-row
#define NIT (NFEAT / BK)

__device__ __forceinline__ void cp_async16(void* smem_dst, const void* gsrc, int src_bytes) {
    uint32_t saddr = (uint32_t)__cvta_generic_to_shared(smem_dst);
    asm volatile("cp.async.cg.shared.global [%0], [%1], 16, %2;\n"
                 :: "r"(saddr), "l"(gsrc), "r"(src_bytes));
}
#define CP_COMMIT() asm volatile("cp.async.commit_group;\n")
#define CP_WAIT(n)  asm volatile("cp.async.wait_group %0;\n" :: "n"(n))

__device__ __forceinline__ void mma_f16(float c[4], uint32_t a0, uint32_t a1,
                                        uint32_t a2, uint32_t a3,
                                        uint32_t b0, uint32_t b1) {
    asm volatile(
        "mma.sync.aligned.m16n8k16.row.col.f32.f16.f16.f32 "
        "{%0,%1,%2,%3}, {%4,%5,%6,%7}, {%8,%9}, {%0,%1,%2,%3};\n"
        : "+f"(c[0]), "+f"(c[1]), "+f"(c[2]), "+f"(c[3])
        : "r"(a0), "r"(a1), "r"(a2), "r"(a3), "r"(b0), "r"(b1));
}

__global__ __launch_bounds__(256) void k_gemm1(const float* __restrict__ A) {
    __shared__ uint32_t Asw[2][BM * ASW_STRIDE];        // fp16x2 A tiles (20 KB)
    __shared__ uint32_t Bs[2][(BK / 2) * BS_STRIDE];    // fp16x2 B tiles (17 KB)

    const int tid = threadIdx.x;
    const int lane = tid & 31;
    const int wid = tid >> 5;
    const int warp_m = wid >> 1;
    const int warp_n = wid & 1;
    const int block_row = blockIdx.x * BM;
    const int lq = lane >> 2;
    const int lr = lane & 3;

    // per-thread A-tile coords: 4 float4 loads, row m = f>>3, float4 col c4 = f&7
    const int a_m0 = tid >> 3;         // rows a_m0, a_m0+32, +64, +96 (r*256>>3 = r*32)
    const int a_c4 = tid & 7;
    const int a_ok_base = block_row;

    float acc[2][8][4];
    #pragma unroll
    for (int i = 0; i < 2; i++)
        #pragma unroll
        for (int j = 0; j < 8; j++)
            #pragma unroll
            for (int r = 0; r < 4; r++) acc[i][j][r] = 0.f;

    float4 areg[4];

    #define LOAD_A_REGS(k0)                                                      \
    do {                                                                         \
        _Pragma("unroll")                                                        \
        for (int r = 0; r < 4; r++) {                                            \
            int m = a_m0 + r * 32;                                               \
            int grow = a_ok_base + m;                                            \
            areg[r] = (grow < N_NODES)                                           \
                ? reinterpret_cast<const float4*>(A + (size_t)grow * NFEAT + (k0))[a_c4] \
                : make_float4(0.f, 0.f, 0.f, 0.f);                               \
        }                                                                        \
    } while (0)

    #define STORE_A_SMEM(st)                                                     \
    do {                                                                         \
        _Pragma("unroll")                                                        \
        for (int r = 0; r < 4; r++) {                                            \
            int m = a_m0 + r * 32;                                               \
            Asw[st][m * ASW_STRIDE + a_c4 * 2]     = pack_f16x2(areg[r].x, areg[r].y); \
            Asw[st][m * ASW_STRIDE + a_c4 * 2 + 1] = pack_f16x2(areg[r].z, areg[r].w); \
        }                                                                        \
    } while (0)

    #define LOAD_B(st, k0)                                                       \
    do {                                                                         \
        _Pragma("unroll")                                                        \
        for (int r = 0; r < 2; r++) {                                            \
            int f = tid + r * 256;                                               \
            int kk = f >> 5, c4 = f & 31;                                        \
            cp_async16(&Bs[st][kk * BS_STRIDE + c4 * 4],                         \
                       g_W1h + ((k0) / 2 + kk) * NHID + c4 * 4, 16);             \
        }                                                                        \
    } while (0)

    // prologue: stage 0
    LOAD_A_REGS(0);
    LOAD_B(0, 0);
    CP_COMMIT();
    STORE_A_SMEM(0);

    for (int it = 0; it < NIT; it++) {
        int st = it & 1;
        if (it + 1 < NIT) {
            LOAD_A_REGS((it + 1) * BK);     // LDG in flight during compute
            LOAD_B(st ^ 1, (it + 1) * BK);
            CP_COMMIT();
            CP_WAIT(1);
        } else {
            CP_WAIT(0);
        }
        __syncthreads();

        #pragma unroll
        for (int ks = 0; ks < 2; ks++) {
            const int kb2 = ks * 8;             // fp16x2 word offset
            uint32_t b0[8], b1[8];
            #pragma unroll
            for (int j = 0; j < 8; j++) {
                int n = warp_n * 64 + j * 8 + lq;
                b0[j] = Bs[st][(kb2 + lr) * BS_STRIDE + n];
                b1[j] = Bs[st][(kb2 + lr + 4) * BS_STRIDE + n];
            }
            #pragma unroll
            for (int i = 0; i < 2; i++) {
                int m = warp_m * 32 + i * 16 + lq;
                uint32_t a0 = Asw[st][m * ASW_STRIDE + kb2 + lr];
                uint32_t a1 = Asw[st][(m + 8) * ASW_STRIDE + kb2 + lr];
                uint32_t a2 = Asw[st][m * ASW_STRIDE + kb2 + lr + 4];
                uint32_t a3 = Asw[st][(m + 8) * ASW_STRIDE + kb2 + lr + 4];
                #pragma unroll
                for (int j = 0; j < 8; j++)
                    mma_f16(acc[i][j], a0, a1, a2, a3, b0[j], b1[j]);
            }
        }
        __syncthreads();

        if (it + 1 < NIT) STORE_A_SMEM(st ^ 1);
    }

    // epilogue: pack column pairs (col, col+1) into fp16x2 words
    #pragma unroll
    for (int i = 0; i < 2; i++) {
        int row0 = block_row + warp_m * 32 + i * 16 + lq;
        #pragma unroll
        for (int j = 0; j < 8; j++) {
            int w = warp_n * 32 + j * 4 + lr;       // word index = col/2
            if (row0 < N_NODES)
                g_H1h[(size_t)row0 * (NHID / 2) + w] = pack_f16x2(acc[i][j][0], acc[i][j][1]);
            if (row0 + 8 < N_NODES)
                g_H1h[(size_t)(row0 + 8) * (NHID / 2) + w] = pack_f16x2(acc[i][j][2], acc[i][j][3]);
        }
    }
    #undef LOAD_A_REGS
    #undef STORE_A_SMEM
    #undef LOAD_B
}

// ---------------- SpMM layer 1 (CSR gather of fp16x2 H1, MLP=4) ------------
__global__ void k_spmm1(const float* __restrict__ bias) {
    int gw = (blockIdx.x * blockDim.x + threadIdx.x) >> 5;
    int lane = threadIdx.x & 31;
    if (gw >= N_NODES) return;

    int s = g_rowptr[gw];
    int e = g_rowptr[gw + 1];
    float4 acc = make_float4(0.f, 0.f, 0.f, 0.f);

    int i = s;
    for (; i + 3 < e; i += 4) {
        int c0 = g_cols[i],     c1 = g_cols[i + 1];
        int c2 = g_cols[i + 2], c3 = g_cols[i + 3];
        float v0 = g_vals[i],     v1 = g_vals[i + 1];
        float v2 = g_vals[i + 2], v3 = g_vals[i + 3];
        uint2 w0 = reinterpret_cast<const uint2*>(g_H1h + (size_t)c0 * (NHID / 2))[lane];
        uint2 w1 = reinterpret_cast<const uint2*>(g_H1h + (size_t)c1 * (NHID / 2))[lane];
        uint2 w2 = reinterpret_cast<const uint2*>(g_H1h + (size_t)c2 * (NHID / 2))[lane];
        uint2 w3 = reinterpret_cast<const uint2*>(g_H1h + (size_t)c3 * (NHID / 2))[lane];
        float2 a0 = __half22float2(*reinterpret_cast<__half2*>(&w0.x));
        float2 b0 = __half22float2(*reinterpret_cast<__half2*>(&w0.y));
        float2 a1 = __half22float2(*reinterpret_cast<__half2*>(&w1.x));
        float2 b1 = __half22float2(*reinterpret_cast<__half2*>(&w1.y));
        float2 a2 = __half22float2(*reinterpret_cast<__half2*>(&w2.x));
        float2 b2 = __half22float2(*reinterpret_cast<__half2*>(&w2.y));
        float2 a3 = __half22float2(*reinterpret_cast<__half2*>(&w3.x));
        float2 b3 = __half22float2(*reinterpret_cast<__half2*>(&w3.y));
        acc.x = fmaf(v0, a0.x, fmaf(v1, a1.x, fmaf(v2, a2.x, fmaf(v3, a3.x, acc.x))));
        acc.y = fmaf(v0, a0.y, fmaf(v1, a1.y, fmaf(v2, a2.y, fmaf(v3, a3.y, acc.y))));
        acc.z = fmaf(v0, b0.x, fmaf(v1, b1.x, fmaf(v2, b2.x, fmaf(v3, b3.x, acc.z))));
        acc.w = fmaf(v0, b0.y, fmaf(v1, b1.y, fmaf(v2, b2.y, fmaf(v3, b3.y, acc.w))));
    }
    for (; i < e; i++) {
        float v = g_vals[i];
        uint2 w = reinterpret_cast<const uint2*>(g_H1h + (size_t)g_cols[i] * (NHID / 2))[lane];
        float2 a = __half22float2(*reinterpret_cast<__half2*>(&w.x));
        float2 b = __half22float2(*reinterpret_cast<__half2*>(&w.y));
        acc.x = fmaf(v, a.x, acc.x);
        acc.y = fmaf(v, a.y, acc.y);
        acc.z = fmaf(v, b.x, acc.z);
        acc.w = fmaf(v, b.y, acc.w);
    }
    float4 b = reinterpret_cast<const float4*>(bias)[lane];
    float4 r;
    r.x = fmaxf(acc.x + b.x, 0.f);
    r.y = fmaxf(acc.y + b.y, 0.f);
    r.z = fmaxf(acc.z + b.z, 0.f);
    r.w = fmaxf(acc.w + b.w, 0.f);
    reinterpret_cast<float4*>(g_H + (size_t)gw * NHID)[lane] = r;
}

// ---------------- GEMM2 (register-tiled): [100000,128]x[128,40] -> g_S2 ---
__global__ __launch_bounds__(256) void k_gemm2(const float* __restrict__ W2) {
    __shared__ float W2s[NHID * NCLASS];  // 20KB
    int tid = threadIdx.x;
    int rows0 = blockIdx.x * 128;

    for (int i = tid; i < NHID * NCLASS / 4; i += 256)
        reinterpret_cast<float4*>(W2s)[i] = reinterpret_cast<const float4*>(W2)[i];
    __syncthreads();

    int tx = tid & 7;
    int ty = tid >> 3;
    const int c0 = tx * 5;

    float acc[4][5];
    #pragma unroll
    for (int i = 0; i < 4; i++)
        #pragma unroll
        for (int j = 0; j < 5; j++) acc[i][j] = 0.f;

    int r[4]; bool ok[4];
    #pragma unroll
    for (int i = 0; i < 4; i++) {
        r[i] = rows0 + ty + 32 * i;
        ok[i] = r[i] < N_NODES;
    }

    for (int k4 = 0; k4 < NHID / 4; k4++) {
        float4 h[4];
        #pragma unroll
        for (int i = 0; i < 4; i++)
            h[i] = ok[i] ? reinterpret_cast<const float4*>(g_H + (size_t)r[i] * NHID)[k4]
                         : make_float4(0.f, 0.f, 0.f, 0.f);
        #pragma unroll
        for (int kk = 0; kk < 4; kk++) {
            int k = k4 * 4 + kk;
            float w[5];
            #pragma unroll
            for (int j = 0; j < 5; j++) w[j] = W2s[k * NCLASS + c0 + j];
            #pragma unroll
            for (int i = 0; i < 4; i++) {
                float hv = (kk == 0) ? h[i].x : (kk == 1) ? h[i].y : (kk == 2) ? h[i].z : h[i].w;
                #pragma unroll
                for (int j = 0; j < 5; j++) acc[i][j] = fmaf(hv, w[j], acc[i][j]);
            }
        }
    }
    #pragma unroll
    for (int i = 0; i < 4; i++)
        if (ok[i]) {
            #pragma unroll
            for (int j = 0; j < 5; j++)
                g_S2[(size_t)r[i] * NCLASS + c0 + j] = acc[i][j];
        }
}

// ---------------- SpMM layer 2 + bias + log_softmax fused (F=40, MLP=4) ---
__global__ void k_spmm2ls(const float* __restrict__ bias, float* __restrict__ out) {
    int gw = (blockIdx.x * blockDim.x + threadIdx.x) >> 5;
    int lane = threadIdx.x & 31;
    if (gw >= N_NODES) return;

    int s = g_rowptr[gw];
    int e = g_rowptr[gw + 1];
    float a0 = 0.f, a1 = 0.f;

    int i = s;
    for (; i + 3 < e; i += 4) {
        int c0 = g_cols[i],     c1 = g_cols[i + 1];
        int c2 = g_cols[i + 2], c3 = g_cols[i + 3];
        float v0 = g_vals[i],     v1 = g_vals[i + 1];
        float v2 = g_vals[i + 2], v3 = g_vals[i + 3];
        const float* d0 = g_S2 + (size_t)c0 * NCLASS;
        const float* d1 = g_S2 + (size_t)c1 * NCLASS;
        const float* d2 = g_S2 + (size_t)c2 * NCLASS;
        const float* d3 = g_S2 + (size_t)c3 * NCLASS;
        float p0 = d0[lane], p1 = d1[lane], p2 = d2[lane], p3 = d3[lane];
        float q0 = 0.f, q1 = 0.f, q2 = 0.f, q3 = 0.f;
        if (lane < 8) {
            q0 = d0[lane + 32]; q1 = d1[lane + 32];
            q2 = d2[lane + 32]; q3 = d3[lane + 32];
        }
        a0 = fmaf(v0, p0, fmaf(v1, p1, fmaf(v2, p2, fmaf(v3, p3, a0))));
        a1 = fmaf(v0, q0, fmaf(v1, q1, fmaf(v2, q2, fmaf(v3, q3, a1))));
    }
    for (; i < e; i++) {
        int c = g_cols[i];
        float v = g_vals[i];
        const float* d = g_S2 + (size_t)c * NCLASS;
        a0 = fmaf(v, d[lane], a0);
        if (lane < 8) a1 = fmaf(v, d[lane + 32], a1);
    }

    float v0 = a0 + bias[lane];
    float v1 = (lane < 8) ? (a1 + bias[lane + 32]) : -INFINITY;

    float m = fmaxf(v0, v1);
    #pragma unroll
    for (int off = 16; off > 0; off >>= 1)
        m = fmaxf(m, __shfl_xor_sync(0xFFFFFFFF, m, off));
    float sum = expf(v0 - m) + ((lane < 8) ? expf(v1 - m) : 0.f);
    #pragma unroll
    for (int off = 16; off > 0; off >>= 1)
        sum += __shfl_xor_sync(0xFFFFFFFF, sum, off);
    float lse = m + logf(sum);

    float* p = out + (size_t)gw * NCLASS;
    p[lane] = v0 - lse;
    if (lane < 8) p[lane + 32] = v1 - lse;
}

// ---------------- stream/event singletons (host resources, created once) ---
static cudaStream_t side_stream() {
    static cudaStream_t s = [] {
        cudaStream_t t;
        cudaStreamCreateWithFlags(&t, cudaStreamNonBlocking);
        return t;
    }();
    return s;
}
static cudaEvent_t fork_event() {
    static cudaEvent_t e = [] {
        cudaEvent_t t;
        cudaEventCreateWithFlags(&t, cudaEventDisableTiming);
        return t;
    }();
    return e;
}
static cudaEvent_t join_event() {
    static cudaEvent_t e = [] {
        cudaEvent_t t;
        cudaEventCreateWithFlags(&t, cudaEventDisableTiming);
        return t;
    }();
    return e;
}

// ---------------- launch ----------------
extern "C" void kernel_launch(void* const* d_in, const int* in_sizes, int n_in,
                              void* d_out, int out_size) {
    const float* x    = (const float*)d_in[0];
    const void*  arow = d_in[1];
    const void*  acol = d_in[2];
    const float* aval = (const float*)d_in[3];
    const float* W1   = (const float*)d_in[4];
    const float* b1   = (const float*)d_in[5];
    const float* W2   = (const float*)d_in[6];
    const float* b2   = (const float*)d_in[7];
    float* out = (float*)d_out;

    cudaStream_t s1 = side_stream();
    cudaEvent_t evF = fork_event();
    cudaEvent_t evJ = join_event();

    // fork: CSR build on side stream, GEMM path on main stream
    cudaEventRecord(evF, 0);
    cudaStreamWaitEvent(s1, evF, 0);

    // branch B (side): CSR build
    k_init<<<(N_NODES + 255) / 256, 256, 0, s1>>>((const int*)arow);
    k_hist<<<(N_EDGES / 2 + 255) / 256, 256, 0, s1>>>(arow);
    k_scan1<<<SCAN_NBLK, SCAN_BLK, 0, s1>>>();
    k_scan2<<<1, 128, 0, s1>>>();
    k_scan3<<<(N_NODES + 255) / 256, 256, 0, s1>>>();
    k_scatter<<<(N_EDGES / 2 + 255) / 256, 256, 0, s1>>>(arow, acol, aval);
    cudaEventRecord(evJ, s1);

    // branch A (main): W1 pack + GEMM1
    k_w1pack<<<((NFEAT / 2) * NHID + 255) / 256, 256>>>(W1);
    k_gemm1<<<(N_NODES + BM - 1) / BM, 256>>>(x);

    // join: SpMM needs both branches
    cudaStreamWaitEvent(0, evJ, 0);

    k_spmm1<<<(N_NODES * 32 + 255) / 256, 256>>>(b1);
    k_gemm2<<<(N_NODES + 127) / 128, 256>>>(W2);
    k_spmm2ls<<<(N_NODES * 32 + 255) / 256, 256>>>(b2, out);
}

// round 17
// speedup vs baseline: 1.2215x; 1.1483x over previous
#include <cuda_runtime.h>
#include <cuda_fp16.h>
#include <math.h>
#include <stdint.h>

#define N_NODES 100000
#define N_EDGES 1600000
#define NFEAT   512
#define NHID    128
#define NCLASS  40

#define SCAN_BLK   1024
#define SCAN_NBLK  ((N_NODES + SCAN_BLK - 1) / SCAN_BLK)   // 98

// ---------------- scratch (static __device__, no allocs) ----------------
__device__ uint32_t g_H1h[(size_t)N_NODES * (NHID / 2)]; // X@W1 as fp16x2
__device__ uint32_t g_Hh [(size_t)N_NODES * (NHID / 2)]; // relu(A@H1+b1) as fp16x2
__device__ float    g_S2[(size_t)N_NODES * NCLASS];      // H @ W2 (fp32)
__device__ uint32_t g_W1h[(NFEAT / 2) * NHID];           // W1 fp16x2, k-pair packed
__device__ uint32_t g_W2h[(NHID / 2) * NCLASS];          // W2 fp16x2, k-pair packed [64][40]
__device__ int      g_rowptr[N_NODES + 1];
__device__ int      g_fill[N_NODES];
__device__ int      g_cols[N_EDGES];
__device__ float    g_vals[N_EDGES];
__device__ int      g_bsum[SCAN_NBLK];
__device__ int      g_is64;

__device__ __forceinline__ uint32_t pack_f16x2(float lo, float hi) {
    uint32_t d;
    asm("cvt.rn.f16x2.f32 %0, %1, %2;" : "=r"(d) : "f"(hi), "f"(lo));
    return d;
}

// ---------------- init: zero counts + dtype detection ----------------
__global__ void k_init(const int* __restrict__ rowi) {
    int i = blockIdx.x * blockDim.x + threadIdx.x;
    if (i < N_NODES) g_fill[i] = 0;
    if (blockIdx.x == 0) {
        __shared__ int red[256];
        int acc = 0;
        for (int t = threadIdx.x; t < 1024; t += 256) acc |= rowi[2 * t + 1];
        red[threadIdx.x] = acc;
        __syncthreads();
        for (int s = 128; s > 0; s >>= 1) {
            if (threadIdx.x < s) red[threadIdx.x] |= red[threadIdx.x + s];
            __syncthreads();
        }
        if (threadIdx.x == 0) g_is64 = (red[0] == 0) ? 1 : 0;
    }
}

// ---------------- W1 pack: fp32 [512][128] -> fp16x2 words [256][128] ------
__global__ void k_w1pack(const float* __restrict__ W1) {
    int i = blockIdx.x * blockDim.x + threadIdx.x;
    if (i < (NFEAT / 2) * NHID) {
        int kk2 = i >> 7;
        int n   = i & 127;
        float f0 = W1[(2 * kk2) * NHID + n];
        float f1 = W1[(2 * kk2 + 1) * NHID + n];
        g_W1h[i] = pack_f16x2(f0, f1);   // lo = k even, hi = k odd
    }
}

// ---------------- W2 pack: fp32 [128][40] -> fp16x2 words [64][40] ---------
__global__ void k_w2pack(const float* __restrict__ W2) {
    int i = blockIdx.x * blockDim.x + threadIdx.x;
    if (i < (NHID / 2) * NCLASS) {
        int k2 = i / NCLASS;
        int n  = i % NCLASS;
        float f0 = W2[(2 * k2) * NCLASS + n];
        float f1 = W2[(2 * k2 + 1) * NCLASS + n];
        g_W2h[i] = pack_f16x2(f0, f1);
    }
}

// ---------------- CSR build (2 edges per thread) ----------------
__global__ void k_hist(const void* __restrict__ row) {
    int t = blockIdx.x * blockDim.x + threadIdx.x;
    if (t >= N_EDGES / 2) return;
    int r0, r1;
    if (g_is64) {
        int4 v = ((const int4*)row)[t];
        r0 = v.x; r1 = v.z;
    } else {
        int2 v = ((const int2*)row)[t];
        r0 = v.x; r1 = v.y;
    }
    atomicAdd(&g_fill[r0], 1);
    atomicAdd(&g_fill[r1], 1);
}

__global__ __launch_bounds__(SCAN_BLK) void k_scan1() {
    __shared__ int wsum[32];
    int tid = threadIdx.x;
    int lane = tid & 31, warp = tid >> 5;
    int i = blockIdx.x * SCAN_BLK + tid;
    int v = (i < N_NODES) ? g_fill[i] : 0;

    int incl = v;
    #pragma unroll
    for (int off = 1; off < 32; off <<= 1) {
        int t = __shfl_up_sync(0xFFFFFFFF, incl, off);
        if (lane >= off) incl += t;
    }
    if (lane == 31) wsum[warp] = incl;
    __syncthreads();
    if (warp == 0) {
        int w = wsum[lane];
        #pragma unroll
        for (int off = 1; off < 32; off <<= 1) {
            int t = __shfl_up_sync(0xFFFFFFFF, w, off);
            if (lane >= off) w += t;
        }
        wsum[lane] = w;
    }
    __syncthreads();
    int base = (warp > 0) ? wsum[warp - 1] : 0;
    int excl = base + incl - v;
    if (i < N_NODES) g_rowptr[i] = excl;
    if (tid == SCAN_BLK - 1) g_bsum[blockIdx.x] = base + incl;
}

__global__ void k_scan2() {
    __shared__ int s[128];
    int tid = threadIdx.x;
    int v = (tid < SCAN_NBLK) ? g_bsum[tid] : 0;
    s[tid] = v;
    __syncthreads();
    for (int off = 1; off < 128; off <<= 1) {
        int t = (tid >= off) ? s[tid - off] : 0;
        __syncthreads();
        s[tid] += t;
        __syncthreads();
    }
    if (tid < SCAN_NBLK) g_bsum[tid] = s[tid] - v;  // exclusive
}

__global__ void k_scan3() {
    int i = blockIdx.x * blockDim.x + threadIdx.x;
    if (i < N_NODES) {
        int v = g_rowptr[i] + g_bsum[i >> 10];
        g_rowptr[i] = v;
        g_fill[i]   = v;
    }
    if (i == 0) g_rowptr[N_NODES] = N_EDGES;
}

__global__ void k_scatter(const void* __restrict__ row,
                          const void* __restrict__ col,
                          const float* __restrict__ val) {
    int t = blockIdx.x * blockDim.x + threadIdx.x;
    if (t >= N_EDGES / 2) return;
    int r0, r1, c0, c1;
    if (g_is64) {
        int4 rv = ((const int4*)row)[t];
        int4 cv = ((const int4*)col)[t];
        r0 = rv.x; r1 = rv.z; c0 = cv.x; c1 = cv.z;
    } else {
        int2 rv = ((const int2*)row)[t];
        int2 cv = ((const int2*)col)[t];
        r0 = rv.x; r1 = rv.y; c0 = cv.x; c1 = cv.y;
    }
    float2 vv = ((const float2*)val)[t];
    int p0 = atomicAdd(&g_fill[r0], 1);
    g_cols[p0] = c0; g_vals[p0] = vv.x;
    int p1 = atomicAdd(&g_fill[r1], 1);
    g_cols[p1] = c1; g_vals[p1] = vv.y;
}

// ---------------- common mma ----------------
__device__ __forceinline__ void mma_f16(float c[4], uint32_t a0, uint32_t a1,
                                        uint32_t a2, uint32_t a3,
                                        uint32_t b0, uint32_t b1) {
    asm volatile(
        "mma.sync.aligned.m16n8k16.row.col.f32.f16.f16.f32 "
        "{%0,%1,%2,%3}, {%4,%5,%6,%7}, {%8,%9}, {%0,%1,%2,%3};\n"
        : "+f"(c[0]), "+f"(c[1]), "+f"(c[2]), "+f"(c[3])
        : "r"(a0), "r"(a1), "r"(a2), "r"(a3), "r"(b0), "r"(b1));
}

__device__ __forceinline__ void cp_async16(void* smem_dst, const void* gsrc) {
    uint32_t saddr = (uint32_t)__cvta_generic_to_shared(smem_dst);
    asm volatile("cp.async.cg.shared.global [%0], [%1], 16;\n" :: "r"(saddr), "l"(gsrc));
}
#define CP_COMMIT() asm volatile("cp.async.commit_group;\n")
#define CP_WAIT(n)  asm volatile("cp.async.wait_group %0;\n" :: "n"(n))

// ---------------- GEMM1 (fp16 mma.sync; fp16 A in smem; single wave) -------
#define BM 128
#define BK 32
#define ASW_STRIDE 20   // fp16x2 words per A row (16 + 4 pad)
#define BS_STRIDE 136   // fp16x2 words per B pair-row
#define NIT (NFEAT / BK)

__global__ __launch_bounds__(256) void k_gemm1(const float* __restrict__ A) {
    __shared__ uint32_t Asw[2][BM * ASW_STRIDE];        // 20 KB
    __shared__ uint32_t Bs[2][(BK / 2) * BS_STRIDE];    // 17 KB

    const int tid = threadIdx.x;
    const int lane = tid & 31;
    const int wid = tid >> 5;
    const int warp_m = wid >> 1;
    const int warp_n = wid & 1;
    const int block_row = blockIdx.x * BM;
    const int lq = lane >> 2;
    const int lr = lane & 3;

    const int a_m0 = tid >> 3;
    const int a_c4 = tid & 7;

    float acc[2][8][4];
    #pragma unroll
    for (int i = 0; i < 2; i++)
        #pragma unroll
        for (int j = 0; j < 8; j++)
            #pragma unroll
            for (int r = 0; r < 4; r++) acc[i][j][r] = 0.f;

    float4 areg[4];

    #define LOAD_A_REGS(k0)                                                      \
    do {                                                                         \
        _Pragma("unroll")                                                        \
        for (int r = 0; r < 4; r++) {                                            \
            int m = a_m0 + r * 32;                                               \
            int grow = block_row + m;                                            \
            areg[r] = (grow < N_NODES)                                           \
                ? reinterpret_cast<const float4*>(A + (size_t)grow * NFEAT + (k0))[a_c4] \
                : make_float4(0.f, 0.f, 0.f, 0.f);                               \
        }                                                                        \
    } while (0)

    #define STORE_A_SMEM(st)                                                     \
    do {                                                                         \
        _Pragma("unroll")                                                        \
        for (int r = 0; r < 4; r++) {                                            \
            int m = a_m0 + r * 32;                                               \
            Asw[st][m * ASW_STRIDE + a_c4 * 2]     = pack_f16x2(areg[r].x, areg[r].y); \
            Asw[st][m * ASW_STRIDE + a_c4 * 2 + 1] = pack_f16x2(areg[r].z, areg[r].w); \
        }                                                                        \
    } while (0)

    #define LOAD_B(st, k0)                                                       \
    do {                                                                         \
        _Pragma("unroll")                                                        \
        for (int r = 0; r < 2; r++) {                                            \
            int f = tid + r * 256;                                               \
            int kk = f >> 5, c4 = f & 31;                                        \
            cp_async16(&Bs[st][kk * BS_STRIDE + c4 * 4],                         \
                       g_W1h + ((k0) / 2 + kk) * NHID + c4 * 4);                 \
        }                                                                        \
    } while (0)

    LOAD_A_REGS(0);
    LOAD_B(0, 0);
    CP_COMMIT();
    STORE_A_SMEM(0);

    for (int it = 0; it < NIT; it++) {
        int st = it & 1;
        if (it + 1 < NIT) {
            LOAD_A_REGS((it + 1) * BK);
            LOAD_B(st ^ 1, (it + 1) * BK);
            CP_COMMIT();
            CP_WAIT(1);
        } else {
            CP_WAIT(0);
        }
        __syncthreads();

        #pragma unroll
        for (int ks = 0; ks < 2; ks++) {
            const int kb2 = ks * 8;
            uint32_t b0[8], b1[8];
            #pragma unroll
            for (int j = 0; j < 8; j++) {
                int n = warp_n * 64 + j * 8 + lq;
                b0[j] = Bs[st][(kb2 + lr) * BS_STRIDE + n];
                b1[j] = Bs[st][(kb2 + lr + 4) * BS_STRIDE + n];
            }
            #pragma unroll
            for (int i = 0; i < 2; i++) {
                int m = warp_m * 32 + i * 16 + lq;
                uint32_t a0 = Asw[st][m * ASW_STRIDE + kb2 + lr];
                uint32_t a1 = Asw[st][(m + 8) * ASW_STRIDE + kb2 + lr];
                uint32_t a2 = Asw[st][m * ASW_STRIDE + kb2 + lr + 4];
                uint32_t a3 = Asw[st][(m + 8) * ASW_STRIDE + kb2 + lr + 4];
                #pragma unroll
                for (int j = 0; j < 8; j++)
                    mma_f16(acc[i][j], a0, a1, a2, a3, b0[j], b1[j]);
            }
        }
        __syncthreads();

        if (it + 1 < NIT) STORE_A_SMEM(st ^ 1);
    }

    #pragma unroll
    for (int i = 0; i < 2; i++) {
        int row0 = block_row + warp_m * 32 + i * 16 + lq;
        #pragma unroll
        for (int j = 0; j < 8; j++) {
            int w = warp_n * 32 + j * 4 + lr;
            if (row0 < N_NODES)
                g_H1h[(size_t)row0 * (NHID / 2) + w] = pack_f16x2(acc[i][j][0], acc[i][j][1]);
            if (row0 + 8 < N_NODES)
                g_H1h[(size_t)(row0 + 8) * (NHID / 2) + w] = pack_f16x2(acc[i][j][2], acc[i][j][3]);
        }
    }
    #undef LOAD_A_REGS
    #undef STORE_A_SMEM
    #undef LOAD_B
}

// ---------------- SpMM layer 1 (fp16x2 gather -> fp16x2 H) -----------------
__global__ void k_spmm1(const float* __restrict__ bias) {
    int gw = (blockIdx.x * blockDim.x + threadIdx.x) >> 5;
    int lane = threadIdx.x & 31;
    if (gw >= N_NODES) return;

    int s = g_rowptr[gw];
    int e = g_rowptr[gw + 1];
    float4 acc = make_float4(0.f, 0.f, 0.f, 0.f);

    int i = s;
    for (; i + 3 < e; i += 4) {
        int c0 = g_cols[i],     c1 = g_cols[i + 1];
        int c2 = g_cols[i + 2], c3 = g_cols[i + 3];
        float v0 = g_vals[i],     v1 = g_vals[i + 1];
        float v2 = g_vals[i + 2], v3 = g_vals[i + 3];
        uint2 w0 = reinterpret_cast<const uint2*>(g_H1h + (size_t)c0 * (NHID / 2))[lane];
        uint2 w1 = reinterpret_cast<const uint2*>(g_H1h + (size_t)c1 * (NHID / 2))[lane];
        uint2 w2 = reinterpret_cast<const uint2*>(g_H1h + (size_t)c2 * (NHID / 2))[lane];
        uint2 w3 = reinterpret_cast<const uint2*>(g_H1h + (size_t)c3 * (NHID / 2))[lane];
        float2 a0 = __half22float2(*reinterpret_cast<__half2*>(&w0.x));
        float2 b0 = __half22float2(*reinterpret_cast<__half2*>(&w0.y));
        float2 a1 = __half22float2(*reinterpret_cast<__half2*>(&w1.x));
        float2 b1 = __half22float2(*reinterpret_cast<__half2*>(&w1.y));
        float2 a2 = __half22float2(*reinterpret_cast<__half2*>(&w2.x));
        float2 b2 = __half22float2(*reinterpret_cast<__half2*>(&w2.y));
        float2 a3 = __half22float2(*reinterpret_cast<__half2*>(&w3.x));
        float2 b3 = __half22float2(*reinterpret_cast<__half2*>(&w3.y));
        acc.x = fmaf(v0, a0.x, fmaf(v1, a1.x, fmaf(v2, a2.x, fmaf(v3, a3.x, acc.x))));
        acc.y = fmaf(v0, a0.y, fmaf(v1, a1.y, fmaf(v2, a2.y, fmaf(v3, a3.y, acc.y))));
        acc.z = fmaf(v0, b0.x, fmaf(v1, b1.x, fmaf(v2, b2.x, fmaf(v3, b3.x, acc.z))));
        acc.w = fmaf(v0, b0.y, fmaf(v1, b1.y, fmaf(v2, b2.y, fmaf(v3, b3.y, acc.w))));
    }
    for (; i < e; i++) {
        float v = g_vals[i];
        uint2 w = reinterpret_cast<const uint2*>(g_H1h + (size_t)g_cols[i] * (NHID / 2))[lane];
        float2 a = __half22float2(*reinterpret_cast<__half2*>(&w.x));
        float2 b = __half22float2(*reinterpret_cast<__half2*>(&w.y));
        acc.x = fmaf(v, a.x, acc.x);
        acc.y = fmaf(v, a.y, acc.y);
        acc.z = fmaf(v, b.x, acc.z);
        acc.w = fmaf(v, b.y, acc.w);
    }
    float4 b = reinterpret_cast<const float4*>(bias)[lane];
    uint2 outw;
    outw.x = pack_f16x2(fmaxf(acc.x + b.x, 0.f), fmaxf(acc.y + b.y, 0.f));
    outw.y = pack_f16x2(fmaxf(acc.z + b.z, 0.f), fmaxf(acc.w + b.w, 0.f));
    reinterpret_cast<uint2*>(g_Hh + (size_t)gw * (NHID / 2))[lane] = outw;
}

// ---------------- GEMM2 (fp16 mma.sync): [100000,128]x[128,40] -> g_S2 -----
// 8 warps x m16; 5 n8-tiles; K=128 in 8 k16 steps. H tile in smem.
#define HS_STRIDE 68   // words/row: banks 4lq+lr distinct
__global__ __launch_bounds__(256) void k_gemm2() {
    __shared__ uint32_t Hs[128 * HS_STRIDE];      // 34.8 KB
    __shared__ uint32_t W2s[(NHID / 2) * NCLASS]; // 10 KB

    const int tid = threadIdx.x;
    const int lane = tid & 31;
    const int wid = tid >> 5;
    const int lq = lane >> 2;
    const int lr = lane & 3;
    const int block_row = blockIdx.x * 128;

    // load W2 pack (2560 words = 640 uint4)
    for (int i = tid; i < (NHID / 2) * NCLASS / 4; i += 256)
        reinterpret_cast<uint4*>(W2s)[i] = reinterpret_cast<const uint4*>(g_W2h)[i];

    // load H tile: 128 rows x 64 words; 2048 uint4, 8 per thread
    #pragma unroll
    for (int r = 0; r < 8; r++) {
        int idx = tid + r * 256;
        int row = idx >> 4;          // 16 uint4 per row
        int c4  = idx & 15;
        int grow = block_row + row;
        uint4 v = make_uint4(0, 0, 0, 0);
        if (grow < N_NODES)
            v = reinterpret_cast<const uint4*>(g_Hh + (size_t)grow * (NHID / 2))[c4];
        *reinterpret_cast<uint4*>(&Hs[row * HS_STRIDE + c4 * 4]) = v;
    }
    __syncthreads();

    float acc[5][4];
    #pragma unroll
    for (int j = 0; j < 5; j++)
        #pragma unroll
        for (int r = 0; r < 4; r++) acc[j][r] = 0.f;

    const int rbase = wid * 16;
    #pragma unroll
    for (int ks = 0; ks < 8; ks++) {
        const int k8 = ks * 8;
        uint32_t a0 = Hs[(rbase + lq) * HS_STRIDE + k8 + lr];
        uint32_t a1 = Hs[(rbase + lq + 8) * HS_STRIDE + k8 + lr];
        uint32_t a2 = Hs[(rbase + lq) * HS_STRIDE + k8 + lr + 4];
        uint32_t a3 = Hs[(rbase + lq + 8) * HS_STRIDE + k8 + lr + 4];
        #pragma unroll
        for (int j = 0; j < 5; j++) {
            uint32_t b0 = W2s[(k8 + lr) * NCLASS + j * 8 + lq];
            uint32_t b1 = W2s[(k8 + lr + 4) * NCLASS + j * 8 + lq];
            mma_f16(acc[j], a0, a1, a2, a3, b0, b1);
        }
    }

    // epilogue: c-frag (lq, 2lr) / (lq+8, 2lr), fp32 float2 stores
    int row0 = block_row + rbase + lq;
    #pragma unroll
    for (int j = 0; j < 5; j++) {
        int col = j * 8 + 2 * lr;
        if (row0 < N_NODES)
            *reinterpret_cast<float2*>(g_S2 + (size_t)row0 * NCLASS + col) =
                make_float2(acc[j][0], acc[j][1]);
        if (row0 + 8 < N_NODES)
            *reinterpret_cast<float2*>(g_S2 + (size_t)(row0 + 8) * NCLASS + col) =
                make_float2(acc[j][2], acc[j][3]);
    }
}

// ---------------- SpMM layer 2 + bias + log_softmax fused (F=40, MLP=4) ---
__global__ void k_spmm2ls(const float* __restrict__ bias, float* __restrict__ out) {
    int gw = (blockIdx.x * blockDim.x + threadIdx.x) >> 5;
    int lane = threadIdx.x & 31;
    if (gw >= N_NODES) return;

    int s = g_rowptr[gw];
    int e = g_rowptr[gw + 1];
    float a0 = 0.f, a1 = 0.f;

    int i = s;
    for (; i + 3 < e; i += 4) {
        int c0 = g_cols[i],     c1 = g_cols[i + 1];
        int c2 = g_cols[i + 2], c3 = g_cols[i + 3];
        float v0 = g_vals[i],     v1 = g_vals[i + 1];
        float v2 = g_vals[i + 2], v3 = g_vals[i + 3];
        const float* d0 = g_S2 + (size_t)c0 * NCLASS;
        const float* d1 = g_S2 + (size_t)c1 * NCLASS;
        const float* d2 = g_S2 + (size_t)c2 * NCLASS;
        const float* d3 = g_S2 + (size_t)c3 * NCLASS;
        float p0 = d0[lane], p1 = d1[lane], p2 = d2[lane], p3 = d3[lane];
        float q0 = 0.f, q1 = 0.f, q2 = 0.f, q3 = 0.f;
        if (lane < 8) {
            q0 = d0[lane + 32]; q1 = d1[lane + 32];
            q2 = d2[lane + 32]; q3 = d3[lane + 32];
        }
        a0 = fmaf(v0, p0, fmaf(v1, p1, fmaf(v2, p2, fmaf(v3, p3, a0))));
        a1 = fmaf(v0, q0, fmaf(v1, q1, fmaf(v2, q2, fmaf(v3, q3, a1))));
    }
    for (; i < e; i++) {
        int c = g_cols[i];
        float v = g_vals[i];
        const float* d = g_S2 + (size_t)c * NCLASS;
        a0 = fmaf(v, d[lane], a0);
        if (lane < 8) a1 = fmaf(v, d[lane + 32], a1);
    }

    float v0 = a0 + bias[lane];
    float v1 = (lane < 8) ? (a1 + bias[lane + 32]) : -INFINITY;

    float m = fmaxf(v0, v1);
    #pragma unroll
    for (int off = 16; off > 0; off >>= 1)
        m = fmaxf(m, __shfl_xor_sync(0xFFFFFFFF, m, off));
    float sum = expf(v0 - m) + ((lane < 8) ? expf(v1 - m) : 0.f);
    #pragma unroll
    for (int off = 16; off > 0; off >>= 1)
        sum += __shfl_xor_sync(0xFFFFFFFF, sum, off);
    float lse = m + logf(sum);

    float* p = out + (size_t)gw * NCLASS;
    p[lane] = v0 - lse;
    if (lane < 8) p[lane + 32] = v1 - lse;
}

// ---------------- stream/event singletons (host resources, created once) ---
static cudaStream_t side_stream() {
    static cudaStream_t s = [] {
        cudaStream_t t;
        cudaStreamCreateWithFlags(&t, cudaStreamNonBlocking);
        return t;
    }();
    return s;
}
static cudaEvent_t fork_event() {
    static cudaEvent_t e = [] {
        cudaEvent_t t;
        cudaEventCreateWithFlags(&t, cudaEventDisableTiming);
        return t;
    }();
    return e;
}
static cudaEvent_t join_event() {
    static cudaEvent_t e = [] {
        cudaEvent_t t;
        cudaEventCreateWithFlags(&t, cudaEventDisableTiming);
        return t;
    }();
    return e;
}

// ---------------- launch ----------------
extern "C" void kernel_launch(void* const* d_in, const int* in_sizes, int n_in,
                              void* d_out, int out_size) {
    const float* x    = (const float*)d_in[0];
    const void*  arow = d_in[1];
    const void*  acol = d_in[2];
    const float* aval = (const float*)d_in[3];
    const float* W1   = (const float*)d_in[4];
    const float* b1   = (const float*)d_in[5];
    const float* W2   = (const float*)d_in[6];
    const float* b2   = (const float*)d_in[7];
    float* out = (float*)d_out;

    cudaStream_t s1 = side_stream();
    cudaEvent_t evF = fork_event();
    cudaEvent_t evJ = join_event();

    // fork: CSR build on side stream, GEMM path on main stream
    cudaEventRecord(evF, 0);
    cudaStreamWaitEvent(s1, evF, 0);

    // branch B (side): CSR build
    k_init<<<(N_NODES + 255) / 256, 256, 0, s1>>>((const int*)arow);
    k_hist<<<(N_EDGES / 2 + 255) / 256, 256, 0, s1>>>(arow);
    k_scan1<<<SCAN_NBLK, SCAN_BLK, 0, s1>>>();
    k_scan2<<<1, 128, 0, s1>>>();
    k_scan3<<<(N_NODES + 255) / 256, 256, 0, s1>>>();
    k_scatter<<<(N_EDGES / 2 + 255) / 256, 256, 0, s1>>>(arow, acol, aval);
    cudaEventRecord(evJ, s1);

    // branch A (main): W1/W2 pack + GEMM1
    k_w1pack<<<((NFEAT / 2) * NHID + 255) / 256, 256>>>(W1);
    k_w2pack<<<((NHID / 2) * NCLASS + 255) / 256, 256>>>(W2);
    k_gemm1<<<(N_NODES + BM - 1) / BM, 256>>>(x);

    // join: SpMM needs both branches
    cudaStreamWaitEvent(0, evJ, 0);

    k_spmm1<<<(N_NODES * 32 + 255) / 256, 256>>>(b1);
    k_gemm2<<<(N_NODES + 127) / 128, 256>>>();
    k_spmm2ls<<<(N_NODES * 32 + 255) / 256, 256>>>(b2, out);
}